// round 11
// baseline (speedup 1.0000x reference)
#include <cuda_runtime.h>
#include <cuda_bf16.h>
#include <math.h>
#include <stdint.h>

#define N_NODES 50000
#define N_EDGES 800000
#define NFEAT 512
#define NHID 128
#define NCLASS 40
#define SCAN_BLOCKS ((N_NODES + 1023) / 1024)   // 49

// ---- scratch (static device arrays; no allocation allowed) ----
__device__ float g_S[(size_t)N_NODES * 128];     // xW1 (support1 only)
__device__ float g_T[(size_t)N_NODES * 80];      // [hW2 | hWr2+br2]
__device__ float g_bc1[256];                     // [0 | br1]
__device__ float g_bc2[80];                      // [0 | br2]
// CSR-by-destination build
__device__ int   g_counts[N_NODES];
__device__ int   g_row_start[N_NODES + 1];
__device__ int   g_cursor[N_NODES];
__device__ int   g_bsum[64];
__device__ int   g_es[N_EDGES];
__device__ float g_ev[N_EDGES];
// bf16 split operands for HMMA GEMM1
__device__ __align__(16) __nv_bfloat16 g_Ah[(size_t)N_NODES * NFEAT];
__device__ __align__(16) __nv_bfloat16 g_Al[(size_t)N_NODES * NFEAT];
__device__ __align__(16) __nv_bfloat16 g_Bth[256 * NFEAT];   // [n][k] W1|Wr1 hi
__device__ __align__(16) __nv_bfloat16 g_Btl[256 * NFEAT];   // lo
// bf16 split operands for HMMA GEMM2
__device__ __align__(16) __nv_bfloat16 g_Hh[(size_t)N_NODES * 256];  // h hi
__device__ __align__(16) __nv_bfloat16 g_Hl[(size_t)N_NODES * 256];  // h lo
__device__ __align__(16) __nv_bfloat16 g_W2th[80 * 256];     // [n][k] W2|Wr2 hi
__device__ __align__(16) __nv_bfloat16 g_W2tl[80 * 256];     // lo

// ================= helpers =================
__device__ __forceinline__ uint32_t smem_u32(const void* p) {
    uint32_t a;
    asm("{ .reg .u64 t; cvta.to.shared.u64 t, %1; cvt.u32.u64 %0, t; }" : "=r"(a) : "l"(p));
    return a;
}
#define CP_ASYNC16(dst, src) \
    asm volatile("cp.async.cg.shared.global [%0], [%1], 16;" :: "r"(dst), "l"(src) : "memory")
#define CP_COMMIT() asm volatile("cp.async.commit_group;" ::: "memory")
#define CP_WAIT(n)  asm volatile("cp.async.wait_group %0;" :: "n"(n) : "memory")

__device__ __forceinline__ void ldmx4(uint32_t addr, uint32_t& r0, uint32_t& r1,
                                      uint32_t& r2, uint32_t& r3) {
    asm volatile("ldmatrix.sync.aligned.m8n8.x4.shared.b16 {%0,%1,%2,%3}, [%4];"
                 : "=r"(r0), "=r"(r1), "=r"(r2), "=r"(r3) : "r"(addr));
}
__device__ __forceinline__ void ldmx2(uint32_t addr, uint32_t& r0, uint32_t& r1) {
    asm volatile("ldmatrix.sync.aligned.m8n8.x2.shared.b16 {%0,%1}, [%2];"
                 : "=r"(r0), "=r"(r1) : "r"(addr));
}
__device__ __forceinline__ void mma16816(float& c0, float& c1, float& c2, float& c3,
                                         uint32_t a0, uint32_t a1, uint32_t a2, uint32_t a3,
                                         uint32_t b0, uint32_t b1) {
    asm volatile("mma.sync.aligned.m16n8k16.row.col.f32.bf16.bf16.f32 "
                 "{%0,%1,%2,%3}, {%4,%5,%6,%7}, {%8,%9}, {%0,%1,%2,%3};"
                 : "+f"(c0), "+f"(c1), "+f"(c2), "+f"(c3)
                 : "r"(a0), "r"(a1), "r"(a2), "r"(a3), "r"(b0), "r"(b1));
}
// split float4 -> 4 hi bf16 (uint2) + 4 lo bf16 (uint2)
__device__ __forceinline__ void split4(float4 f, uint2& hi, uint2& lo) {
    __nv_bfloat16 h0 = __float2bfloat16(f.x), h1 = __float2bfloat16(f.y);
    __nv_bfloat16 h2 = __float2bfloat16(f.z), h3 = __float2bfloat16(f.w);
    __nv_bfloat16 l0 = __float2bfloat16(f.x - __bfloat162float(h0));
    __nv_bfloat16 l1 = __float2bfloat16(f.y - __bfloat162float(h1));
    __nv_bfloat16 l2 = __float2bfloat16(f.z - __bfloat162float(h2));
    __nv_bfloat16 l3 = __float2bfloat16(f.w - __bfloat162float(h3));
    union { __nv_bfloat162 b; uint32_t u; } p;
    p.b.x = h0; p.b.y = h1; hi.x = p.u;
    p.b.x = h2; p.b.y = h3; hi.y = p.u;
    p.b.x = l0; p.b.y = l1; lo.x = p.u;
    p.b.x = l2; p.b.y = l3; lo.y = p.u;
}
// split float2 -> packed bf16x2 hi + lo
__device__ __forceinline__ void split2(float a, float b, uint32_t& hi, uint32_t& lo) {
    __nv_bfloat16 h0 = __float2bfloat16(a), h1 = __float2bfloat16(b);
    __nv_bfloat16 l0 = __float2bfloat16(a - __bfloat162float(h0));
    __nv_bfloat16 l1 = __float2bfloat16(b - __bfloat162float(h1));
    union { __nv_bfloat162 b; uint32_t u; } p;
    p.b.x = h0; p.b.y = h1; hi = p.u;
    p.b.x = l0; p.b.y = l1; lo = p.u;
}

// ---- pack: B1t hi/lo, W2t hi/lo, biases ----
__global__ void pack_kernel(const float* __restrict__ W1, const float* __restrict__ Wr1,
                            const float* __restrict__ br1,
                            const float* __restrict__ W2, const float* __restrict__ Wr2,
                            const float* __restrict__ br2) {
    int idx = blockIdx.x * blockDim.x + threadIdx.x;
    if (idx < NFEAT * 256) {
        int k = idx >> 8, n = idx & 255;
        float w = (n < 128) ? W1[k * 128 + n] : Wr1[k * 128 + (n - 128)];
        __nv_bfloat16 hi = __float2bfloat16(w);
        __nv_bfloat16 lo = __float2bfloat16(w - __bfloat162float(hi));
        g_Bth[(size_t)n * NFEAT + k] = hi;
        g_Btl[(size_t)n * NFEAT + k] = lo;
    }
    if (idx < 256 * 80) {
        int k = idx / 80, j = idx % 80;
        float w = (j < 40) ? W2[k * 40 + j] : Wr2[k * 40 + (j - 40)];
        __nv_bfloat16 hi = __float2bfloat16(w);
        __nv_bfloat16 lo = __float2bfloat16(w - __bfloat162float(hi));
        g_W2th[j * 256 + k] = hi;
        g_W2tl[j * 256 + k] = lo;
    }
    if (idx < 256) g_bc1[idx] = (idx < 128) ? 0.f : br1[idx - 128];
    if (idx < 80)  g_bc2[idx] = (idx < 40) ? 0.f : br2[idx - 40];
}

// ---- zero histogram (side chain) ----
__global__ void zero_counts_kernel() {
    int i = blockIdx.x * blockDim.x + threadIdx.x;
    if (i < N_NODES) g_counts[i] = 0;
}

// ---- convert x -> Ah, Al (bf16 hi/lo), row-major ----
__global__ void convertA_kernel(const float* __restrict__ x) {
    int gid = blockIdx.x * blockDim.x + threadIdx.x;  // 8 fp32 per thread
    if (gid >= N_NODES * (NFEAT / 8)) return;
    const float4* p = (const float4*)&x[(size_t)gid * 8];
    uint2 h0, l0, h1, l1;
    split4(p[0], h0, l0);
    split4(p[1], h1, l1);
    *(uint4*)&g_Ah[(size_t)gid * 8] = make_uint4(h0.x, h0.y, h1.x, h1.y);
    *(uint4*)&g_Al[(size_t)gid * 8] = make_uint4(l0.x, l0.y, l1.x, l1.y);
}

// ---- GEMM1 via mma.sync bf16 3-term ----
// blockIdx.y==0: S[:, :128] (fp32, spmm1 gather source)
// blockIdx.y==1: residual half -> Hh/Hl[:,128:] directly (bias-added bf16 split)
#define ARR_SZ (128 * 40 * 2)        // bytes per smem array (80B padded rows)
#define STG_SZ (4 * ARR_SZ)          // 40960
#define GEMM1_SMEM (2 * STG_SZ)      // 81920

__global__ __launch_bounds__(256, 2) void gemm1_mma() {
    extern __shared__ unsigned char smem[];
    uint32_t sb = smem_u32(smem);
    int tid = threadIdx.x, lane = tid & 31, wid = tid >> 5;
    int warp_m = wid & 3, warp_n = wid >> 2;
    int brow = blockIdx.x * 128;
    int bcol = blockIdx.y * 128;
    int grp = lane >> 3, rr = lane & 7;

    float acc[2][8][4];
#pragma unroll
    for (int i = 0; i < 2; i++)
#pragma unroll
        for (int j = 0; j < 8; j++)
#pragma unroll
            for (int q = 0; q < 4; q++) acc[i][j][q] = 0.f;

    const __nv_bfloat16* gsrc[4] = {g_Ah, g_Al, g_Bth, g_Btl};

#define LOAD_STAGE(stage, k0) do { \
    _Pragma("unroll") \
    for (int arr = 0; arr < 4; arr++) { \
        _Pragma("unroll") \
        for (int rep = 0; rep < 2; rep++) { \
            int q = tid + rep * 256; \
            int row = q >> 2, c16 = q & 3; \
            uint32_t dst = sb + (stage) * STG_SZ + arr * ARR_SZ + row * 80 + c16 * 16; \
            const __nv_bfloat16* src; \
            if (arr < 2) { \
                int rg = brow + row; if (rg >= N_NODES) rg = N_NODES - 1; \
                src = gsrc[arr] + (size_t)rg * NFEAT + (k0) + c16 * 8; \
            } else { \
                src = gsrc[arr] + (size_t)(bcol + row) * NFEAT + (k0) + c16 * 8; \
            } \
            CP_ASYNC16(dst, src); \
        } \
    } \
    CP_COMMIT(); \
} while (0)

    LOAD_STAGE(0, 0);

    int cur = 0;
    for (int s = 0; s < 16; s++) {
        if (s < 15) {
            LOAD_STAGE(1 - cur, (s + 1) * 32);
            CP_WAIT(1);
        } else {
            CP_WAIT(0);
        }
        __syncthreads();

        uint32_t base = sb + cur * STG_SZ;
#pragma unroll
        for (int k16 = 0; k16 < 32; k16 += 16) {
            uint32_t ah[2][4], al[2][4], bh[4][4], bl[4][4];
#pragma unroll
            for (int mi = 0; mi < 2; mi++) {
                uint32_t ao = base + (uint32_t)((warp_m * 32 + mi * 16 + (grp & 1) * 8 + rr) * 80
                                                + (k16 + (grp >> 1) * 8) * 2);
                ldmx4(ao + 0 * ARR_SZ, ah[mi][0], ah[mi][1], ah[mi][2], ah[mi][3]);
                ldmx4(ao + 1 * ARR_SZ, al[mi][0], al[mi][1], al[mi][2], al[mi][3]);
            }
#pragma unroll
            for (int p = 0; p < 4; p++) {
                uint32_t bo = base + (uint32_t)((warp_n * 64 + p * 16 + (grp >> 1) * 8 + rr) * 80
                                                + (k16 + (grp & 1) * 8) * 2);
                ldmx4(bo + 2 * ARR_SZ, bh[p][0], bh[p][1], bh[p][2], bh[p][3]);
                ldmx4(bo + 3 * ARR_SZ, bl[p][0], bl[p][1], bl[p][2], bl[p][3]);
            }
#pragma unroll
            for (int mi = 0; mi < 2; mi++) {
#pragma unroll
                for (int ni = 0; ni < 8; ni++) {
                    uint32_t b0h = bh[ni >> 1][(ni & 1) * 2], b1h = bh[ni >> 1][(ni & 1) * 2 + 1];
                    uint32_t b0l = bl[ni >> 1][(ni & 1) * 2], b1l = bl[ni >> 1][(ni & 1) * 2 + 1];
                    float* c = acc[mi][ni];
                    mma16816(c[0], c[1], c[2], c[3],
                             ah[mi][0], ah[mi][1], ah[mi][2], ah[mi][3], b0h, b1h);
                    mma16816(c[0], c[1], c[2], c[3],
                             ah[mi][0], ah[mi][1], ah[mi][2], ah[mi][3], b0l, b1l);
                    mma16816(c[0], c[1], c[2], c[3],
                             al[mi][0], al[mi][1], al[mi][2], al[mi][3], b0h, b1h);
                }
            }
        }
        __syncthreads();
        cur ^= 1;
    }

#pragma unroll
    for (int mi = 0; mi < 2; mi++) {
        int r0 = brow + warp_m * 32 + mi * 16 + (lane >> 2);
#pragma unroll
        for (int ni = 0; ni < 8; ni++) {
            int c = bcol + warp_n * 64 + ni * 8 + (lane & 3) * 2;
            float bx = g_bc1[c], by = g_bc1[c + 1];
            float* cc = acc[mi][ni];
            if (blockIdx.y == 0) {
                // support1 half: fp32 S (gathered by spmm1)
                if (r0 < N_NODES)
                    *(float2*)&g_S[(size_t)r0 * 128 + c] = make_float2(cc[0] + bx, cc[1] + by);
                if (r0 + 8 < N_NODES)
                    *(float2*)&g_S[(size_t)(r0 + 8) * 128 + c] = make_float2(cc[2] + bx, cc[3] + by);
            } else {
                // residual half: straight to Hh/Hl (bias-added, bf16 split)
                uint32_t hi, lo;
                if (r0 < N_NODES) {
                    split2(cc[0] + bx, cc[1] + by, hi, lo);
                    *(uint32_t*)&g_Hh[(size_t)r0 * 256 + c] = hi;
                    *(uint32_t*)&g_Hl[(size_t)r0 * 256 + c] = lo;
                }
                if (r0 + 8 < N_NODES) {
                    split2(cc[2] + bx, cc[3] + by, hi, lo);
                    *(uint32_t*)&g_Hh[(size_t)(r0 + 8) * 256 + c] = hi;
                    *(uint32_t*)&g_Hl[(size_t)(r0 + 8) * 256 + c] = lo;
                }
            }
        }
    }
}

// ---- GEMM2 via mma.sync bf16 3-term: g_T = h @ [W2|Wr2] + [0|br2] ----
#define A2_SZ (128 * 80)             // 10240 bytes (hi or lo)
#define B2_SZ (80 * 80)              // 6400 bytes
#define STG2_SZ (2 * A2_SZ + 2 * B2_SZ)  // 33280
#define G2_BOFF (2 * A2_SZ)
#define GEMM2_SMEM (2 * STG2_SZ)     // 66560

__global__ __launch_bounds__(256, 2) void gemm2_mma() {
    extern __shared__ unsigned char smem[];
    uint32_t sb = smem_u32(smem);
    int tid = threadIdx.x, lane = tid & 31, wid = tid >> 5;
    int warp_m = wid & 3, warp_n = wid >> 2;
    int brow = blockIdx.x * 128;
    int grp = lane >> 3, rr = lane & 7;

    float acc[2][5][4];
#pragma unroll
    for (int i = 0; i < 2; i++)
#pragma unroll
        for (int j = 0; j < 5; j++)
#pragma unroll
            for (int q = 0; q < 4; q++) acc[i][j][q] = 0.f;

#define LOAD_STAGE2(stage, k0) do { \
    _Pragma("unroll") \
    for (int arr = 0; arr < 2; arr++) { \
        _Pragma("unroll") \
        for (int rep = 0; rep < 2; rep++) { \
            int q = tid + rep * 256; \
            int row = q >> 2, c16 = q & 3; \
            int rg = brow + row; if (rg >= N_NODES) rg = N_NODES - 1; \
            uint32_t dst = sb + (stage) * STG2_SZ + arr * A2_SZ + row * 80 + c16 * 16; \
            const __nv_bfloat16* src = (arr ? g_Hl : g_Hh) + (size_t)rg * 256 + (k0) + c16 * 8; \
            CP_ASYNC16(dst, src); \
        } \
    } \
    _Pragma("unroll") \
    for (int arr = 0; arr < 2; arr++) { \
        _Pragma("unroll") \
        for (int rep = 0; rep < 2; rep++) { \
            int q = tid + rep * 256; \
            if (q < 320) { \
                int row = q >> 2, c16 = q & 3; \
                uint32_t dst = sb + (stage) * STG2_SZ + G2_BOFF + arr * B2_SZ + row * 80 + c16 * 16; \
                const __nv_bfloat16* src = (arr ? g_W2tl : g_W2th) + row * 256 + (k0) + c16 * 8; \
                CP_ASYNC16(dst, src); \
            } \
        } \
    } \
    CP_COMMIT(); \
} while (0)

    LOAD_STAGE2(0, 0);

    int cur = 0;
    for (int s = 0; s < 8; s++) {
        if (s < 7) {
            LOAD_STAGE2(1 - cur, (s + 1) * 32);
            CP_WAIT(1);
        } else {
            CP_WAIT(0);
        }
        __syncthreads();

        uint32_t base = sb + cur * STG2_SZ;
#pragma unroll
        for (int k16 = 0; k16 < 32; k16 += 16) {
            uint32_t ah[2][4], al[2][4], bh[2][4], bl[2][4], bhx[2], blx[2];
#pragma unroll
            for (int mi = 0; mi < 2; mi++) {
                uint32_t ao = base + (uint32_t)((warp_m * 32 + mi * 16 + (grp & 1) * 8 + rr) * 80
                                                + (k16 + (grp >> 1) * 8) * 2);
                ldmx4(ao + 0 * A2_SZ, ah[mi][0], ah[mi][1], ah[mi][2], ah[mi][3]);
                ldmx4(ao + 1 * A2_SZ, al[mi][0], al[mi][1], al[mi][2], al[mi][3]);
            }
#pragma unroll
            for (int p = 0; p < 2; p++) {
                uint32_t bo = base + G2_BOFF
                            + (uint32_t)((warp_n * 40 + p * 16 + (grp >> 1) * 8 + rr) * 80
                                         + (k16 + (grp & 1) * 8) * 2);
                ldmx4(bo + 0 * B2_SZ, bh[p][0], bh[p][1], bh[p][2], bh[p][3]);
                ldmx4(bo + 1 * B2_SZ, bl[p][0], bl[p][1], bl[p][2], bl[p][3]);
            }
            {
                uint32_t bo = base + G2_BOFF
                            + (uint32_t)((warp_n * 40 + 32 + rr) * 80
                                         + (k16 + (grp & 1) * 8) * 2);
                ldmx2(bo + 0 * B2_SZ, bhx[0], bhx[1]);
                ldmx2(bo + 1 * B2_SZ, blx[0], blx[1]);
            }
#pragma unroll
            for (int mi = 0; mi < 2; mi++) {
#pragma unroll
                for (int ni = 0; ni < 5; ni++) {
                    uint32_t b0h, b1h, b0l, b1l;
                    if (ni < 4) {
                        b0h = bh[ni >> 1][(ni & 1) * 2]; b1h = bh[ni >> 1][(ni & 1) * 2 + 1];
                        b0l = bl[ni >> 1][(ni & 1) * 2]; b1l = bl[ni >> 1][(ni & 1) * 2 + 1];
                    } else {
                        b0h = bhx[0]; b1h = bhx[1];
                        b0l = blx[0]; b1l = blx[1];
                    }
                    float* c = acc[mi][ni];
                    mma16816(c[0], c[1], c[2], c[3],
                             ah[mi][0], ah[mi][1], ah[mi][2], ah[mi][3], b0h, b1h);
                    mma16816(c[0], c[1], c[2], c[3],
                             ah[mi][0], ah[mi][1], ah[mi][2], ah[mi][3], b0l, b1l);
                    mma16816(c[0], c[1], c[2], c[3],
                             al[mi][0], al[mi][1], al[mi][2], al[mi][3], b0h, b1h);
                }
            }
        }
        __syncthreads();
        cur ^= 1;
    }

#pragma unroll
    for (int mi = 0; mi < 2; mi++) {
        int r0 = brow + warp_m * 32 + mi * 16 + (lane >> 2);
#pragma unroll
        for (int ni = 0; ni < 5; ni++) {
            int c = warp_n * 40 + ni * 8 + (lane & 3) * 2;
            float bx = g_bc2[c], by = g_bc2[c + 1];
            float* cc = acc[mi][ni];
            if (r0 < N_NODES)
                *(float2*)&g_T[(size_t)r0 * 80 + c] = make_float2(cc[0] + bx, cc[1] + by);
            if (r0 + 8 < N_NODES)
                *(float2*)&g_T[(size_t)(r0 + 8) * 80 + c] = make_float2(cc[2] + bx, cc[3] + by);
        }
    }
}

// ---- histogram ----
__global__ void hist_kernel(const int* __restrict__ dst) {
    int e = blockIdx.x * blockDim.x + threadIdx.x;
    if (e < N_EDGES) atomicAdd(&g_counts[dst[e]], 1);
}

// ---- parallel 3-phase scan ----
__global__ void scan1_kernel() {
    __shared__ int wsum[32];
    int tid = threadIdx.x, lane = tid & 31, w = tid >> 5;
    int i = blockIdx.x * 1024 + tid;
    int c = (i < N_NODES) ? g_counts[i] : 0;
    int v = c;
#pragma unroll
    for (int d = 1; d < 32; d <<= 1) {
        int t = __shfl_up_sync(0xffffffffu, v, d);
        if (lane >= d) v += t;
    }
    if (lane == 31) wsum[w] = v;
    __syncthreads();
    if (w == 0) {
        int s = wsum[lane];
#pragma unroll
        for (int d = 1; d < 32; d <<= 1) {
            int t = __shfl_up_sync(0xffffffffu, s, d);
            if (lane >= d) s += t;
        }
        wsum[lane] = s;
    }
    __syncthreads();
    int incl = v + ((w == 0) ? 0 : wsum[w - 1]);
    if (i < N_NODES) g_row_start[i] = incl - c;
    if (tid == 1023) g_bsum[blockIdx.x] = incl;
}

__global__ void scan2_kernel() {
    int lane = threadIdx.x;
    int a = (2 * lane < SCAN_BLOCKS) ? g_bsum[2 * lane] : 0;
    int b = (2 * lane + 1 < SCAN_BLOCKS) ? g_bsum[2 * lane + 1] : 0;
    int pair = a + b;
    int v = pair;
#pragma unroll
    for (int d = 1; d < 32; d <<= 1) {
        int t = __shfl_up_sync(0xffffffffu, v, d);
        if (lane >= d) v += t;
    }
    int excl = v - pair;
    if (2 * lane < 64) g_bsum[2 * lane] = excl;
    if (2 * lane + 1 < 64) g_bsum[2 * lane + 1] = excl + a;
}

__global__ void scan3_kernel() {
    int i = blockIdx.x * blockDim.x + threadIdx.x;
    if (i < N_NODES) {
        int v = g_row_start[i] + g_bsum[i >> 10];
        g_row_start[i] = v;
        g_cursor[i] = v;
    }
    if (i == 0) g_row_start[N_NODES] = N_EDGES;
}

__global__ void scatter_kernel(const int* __restrict__ src, const int* __restrict__ dst,
                               const float* __restrict__ val) {
    int e = blockIdx.x * blockDim.x + threadIdx.x;
    if (e >= N_EDGES) return;
    int d = dst[e];
    int p = atomicAdd(&g_cursor[d], 1);
    g_es[p] = src[e];
    g_ev[p] = val[e];
}

// ---- SpMM1 (CSR, warp per dst row, 8-edge unroll): writes bf16 hi/lo h[:, :128] ----
__global__ void spmm1_csr(const float* __restrict__ b1) {
    int w = (blockIdx.x * blockDim.x + threadIdx.x) >> 5;
    int lane = threadIdx.x & 31;
    if (w >= N_NODES) return;
    int e = g_row_start[w];
    int end = g_row_start[w + 1];
    float4 acc = *(const float4*)&b1[lane * 4];
    for (; e + 8 <= end; e += 8) {
        int s0 = g_es[e], s1 = g_es[e + 1], s2 = g_es[e + 2], s3 = g_es[e + 3];
        int s4 = g_es[e + 4], s5 = g_es[e + 5], s6 = g_es[e + 6], s7 = g_es[e + 7];
        float v0 = g_ev[e], v1 = g_ev[e + 1], v2 = g_ev[e + 2], v3 = g_ev[e + 3];
        float v4 = g_ev[e + 4], v5 = g_ev[e + 5], v6 = g_ev[e + 6], v7 = g_ev[e + 7];
        float4 x0 = *(const float4*)&g_S[(size_t)s0 * 128 + lane * 4];
        float4 x1 = *(const float4*)&g_S[(size_t)s1 * 128 + lane * 4];
        float4 x2 = *(const float4*)&g_S[(size_t)s2 * 128 + lane * 4];
        float4 x3 = *(const float4*)&g_S[(size_t)s3 * 128 + lane * 4];
        float4 x4 = *(const float4*)&g_S[(size_t)s4 * 128 + lane * 4];
        float4 x5 = *(const float4*)&g_S[(size_t)s5 * 128 + lane * 4];
        float4 x6 = *(const float4*)&g_S[(size_t)s6 * 128 + lane * 4];
        float4 x7 = *(const float4*)&g_S[(size_t)s7 * 128 + lane * 4];
        acc.x = fmaf(v0, x0.x, acc.x); acc.y = fmaf(v0, x0.y, acc.y);
        acc.z = fmaf(v0, x0.z, acc.z); acc.w = fmaf(v0, x0.w, acc.w);
        acc.x = fmaf(v1, x1.x, acc.x); acc.y = fmaf(v1, x1.y, acc.y);
        acc.z = fmaf(v1, x1.z, acc.z); acc.w = fmaf(v1, x1.w, acc.w);
        acc.x = fmaf(v2, x2.x, acc.x); acc.y = fmaf(v2, x2.y, acc.y);
        acc.z = fmaf(v2, x2.z, acc.z); acc.w = fmaf(v2, x2.w, acc.w);
        acc.x = fmaf(v3, x3.x, acc.x); acc.y = fmaf(v3, x3.y, acc.y);
        acc.z = fmaf(v3, x3.z, acc.z); acc.w = fmaf(v3, x3.w, acc.w);
        acc.x = fmaf(v4, x4.x, acc.x); acc.y = fmaf(v4, x4.y, acc.y);
        acc.z = fmaf(v4, x4.z, acc.z); acc.w = fmaf(v4, x4.w, acc.w);
        acc.x = fmaf(v5, x5.x, acc.x); acc.y = fmaf(v5, x5.y, acc.y);
        acc.z = fmaf(v5, x5.z, acc.z); acc.w = fmaf(v5, x5.w, acc.w);
        acc.x = fmaf(v6, x6.x, acc.x); acc.y = fmaf(v6, x6.y, acc.y);
        acc.z = fmaf(v6, x6.z, acc.z); acc.w = fmaf(v6, x6.w, acc.w);
        acc.x = fmaf(v7, x7.x, acc.x); acc.y = fmaf(v7, x7.y, acc.y);
        acc.z = fmaf(v7, x7.z, acc.z); acc.w = fmaf(v7, x7.w, acc.w);
    }
    for (; e < end; e++) {
        int s0 = g_es[e];
        float v0 = g_ev[e];
        float4 x0 = *(const float4*)&g_S[(size_t)s0 * 128 + lane * 4];
        acc.x = fmaf(v0, x0.x, acc.x); acc.y = fmaf(v0, x0.y, acc.y);
        acc.z = fmaf(v0, x0.z, acc.z); acc.w = fmaf(v0, x0.w, acc.w);
    }
    float4 o;
    o.x = fmaxf(acc.x, 0.f); o.y = fmaxf(acc.y, 0.f);
    o.z = fmaxf(acc.z, 0.f); o.w = fmaxf(acc.w, 0.f);
    uint2 hi, lo;
    split4(o, hi, lo);
    *(uint2*)&g_Hh[(size_t)w * 256 + lane * 4] = hi;
    *(uint2*)&g_Hl[(size_t)w * 256 + lane * 4] = lo;
}

// ---- SpMM2 (CSR, warp per dst row, 8-edge unroll) fused final -> out ----
__global__ void spmm2_final(const float* __restrict__ b2, float* __restrict__ out) {
    int w = (blockIdx.x * blockDim.x + threadIdx.x) >> 5;
    int lane = threadIdx.x & 31;
    if (w >= N_NODES) return;
    int e = g_row_start[w];
    int end = g_row_start[w + 1];
    bool act = lane < 20;
    float ax = 0.f, ay = 0.f;
    if (act) { ax = b2[2 * lane]; ay = b2[2 * lane + 1]; }
    for (; e + 8 <= end; e += 8) {
        int s0 = g_es[e], s1 = g_es[e + 1], s2 = g_es[e + 2], s3 = g_es[e + 3];
        int s4 = g_es[e + 4], s5 = g_es[e + 5], s6 = g_es[e + 6], s7 = g_es[e + 7];
        float v0 = g_ev[e], v1 = g_ev[e + 1], v2 = g_ev[e + 2], v3 = g_ev[e + 3];
        float v4 = g_ev[e + 4], v5 = g_ev[e + 5], v6 = g_ev[e + 6], v7 = g_ev[e + 7];
        if (act) {
            float2 t0 = *(const float2*)&g_T[(size_t)s0 * 80 + 2 * lane];
            float2 t1 = *(const float2*)&g_T[(size_t)s1 * 80 + 2 * lane];
            float2 t2 = *(const float2*)&g_T[(size_t)s2 * 80 + 2 * lane];
            float2 t3 = *(const float2*)&g_T[(size_t)s3 * 80 + 2 * lane];
            float2 t4 = *(const float2*)&g_T[(size_t)s4 * 80 + 2 * lane];
            float2 t5 = *(const float2*)&g_T[(size_t)s5 * 80 + 2 * lane];
            float2 t6 = *(const float2*)&g_T[(size_t)s6 * 80 + 2 * lane];
            float2 t7 = *(const float2*)&g_T[(size_t)s7 * 80 + 2 * lane];
            ax = fmaf(v0, t0.x, ax); ay = fmaf(v0, t0.y, ay);
            ax = fmaf(v1, t1.x, ax); ay = fmaf(v1, t1.y, ay);
            ax = fmaf(v2, t2.x, ax); ay = fmaf(v2, t2.y, ay);
            ax = fmaf(v3, t3.x, ax); ay = fmaf(v3, t3.y, ay);
            ax = fmaf(v4, t4.x, ax); ay = fmaf(v4, t4.y, ay);
            ax = fmaf(v5, t5.x, ax); ay = fmaf(v5, t5.y, ay);
            ax = fmaf(v6, t6.x, ax); ay = fmaf(v6, t6.y, ay);
            ax = fmaf(v7, t7.x, ax); ay = fmaf(v7, t7.y, ay);
        }
    }
    for (; e < end; e++) {
        int s0 = g_es[e];
        float v0 = g_ev[e];
        if (act) {
            float2 t0 = *(const float2*)&g_T[(size_t)s0 * 80 + 2 * lane];
            ax = fmaf(v0, t0.x, ax); ay = fmaf(v0, t0.y, ay);
        }
    }
    if (act) {
        float2 r = *(const float2*)&g_T[(size_t)w * 80 + 40 + 2 * lane];
        ax += r.x; ay += r.y;
    }
    float m = act ? fmaxf(ax, ay) : -INFINITY;
#pragma unroll
    for (int o = 16; o > 0; o >>= 1) m = fmaxf(m, __shfl_xor_sync(0xffffffffu, m, o));
    float s = act ? (__expf(ax - m) + __expf(ay - m)) : 0.f;
#pragma unroll
    for (int o = 16; o > 0; o >>= 1) s += __shfl_xor_sync(0xffffffffu, s, o);
    float lse = m + logf(s);
    if (act) {
        out[(size_t)w * 40 + 2 * lane + 0] = ax - lse;
        out[(size_t)w * 40 + 2 * lane + 1] = ay - lse;
    }
}

extern "C" void kernel_launch(void* const* d_in, const int* in_sizes, int n_in,
                              void* d_out, int out_size) {
    const float* x    = (const float*)d_in[0];
    const int*   esrc = (const int*)d_in[1];
    const int*   edst = (const int*)d_in[2];
    const float* eval_= (const float*)d_in[3];
    const float* W1   = (const float*)d_in[4];
    const float* b1   = (const float*)d_in[5];
    const float* Wr1  = (const float*)d_in[6];
    const float* br1  = (const float*)d_in[7];
    const float* W2   = (const float*)d_in[8];
    const float* b2   = (const float*)d_in[9];
    const float* Wr2  = (const float*)d_in[10];
    const float* br2  = (const float*)d_in[11];
    float* out = (float*)d_out;

    static cudaStream_t s_side = nullptr;
    static cudaEvent_t ev_fork = nullptr, ev_join = nullptr;
    static bool init_done = false;
    if (!init_done) {
        cudaFuncSetAttribute(gemm1_mma, cudaFuncAttributeMaxDynamicSharedMemorySize, GEMM1_SMEM);
        cudaFuncSetAttribute(gemm2_mma, cudaFuncAttributeMaxDynamicSharedMemorySize, GEMM2_SMEM);
        cudaStreamCreateWithFlags(&s_side, cudaStreamNonBlocking);
        cudaEventCreateWithFlags(&ev_fork, cudaEventDisableTiming);
        cudaEventCreateWithFlags(&ev_join, cudaEventDisableTiming);
        init_done = true;
    }

    // ---- fork: CSR build chain on side stream ----
    cudaEventRecord(ev_fork, 0);
    cudaStreamWaitEvent(s_side, ev_fork, 0);
    zero_counts_kernel<<<(N_NODES + 255) / 256, 256, 0, s_side>>>();
    hist_kernel<<<(N_EDGES + 255) / 256, 256, 0, s_side>>>(edst);
    scan1_kernel<<<SCAN_BLOCKS, 1024, 0, s_side>>>();
    scan2_kernel<<<1, 32, 0, s_side>>>();
    scan3_kernel<<<(N_NODES + 255) / 256, 256, 0, s_side>>>();
    scatter_kernel<<<(N_EDGES + 255) / 256, 256, 0, s_side>>>(esrc, edst, eval_);
    cudaEventRecord(ev_join, s_side);

    // ---- main chain: pack -> convert -> GEMM1 ----
    pack_kernel<<<512, 256>>>(W1, Wr1, br1, W2, Wr2, br2);
    convertA_kernel<<<(N_NODES * (NFEAT / 8) + 255) / 256, 256>>>(x);
    {
        dim3 grid((N_NODES + 127) / 128, 2);
        gemm1_mma<<<grid, 256, GEMM1_SMEM>>>();
    }

    // ---- join: spmm1 needs CSR + S ----
    cudaStreamWaitEvent(0, ev_join, 0);
    spmm1_csr<<<(N_NODES + 7) / 8, 256>>>(b1);
    gemm2_mma<<<(N_NODES + 127) / 128, 256, GEMM2_SMEM>>>();
    spmm2_final<<<(N_NODES + 7) / 8, 256>>>(b2, out);
}

// round 12
// speedup vs baseline: 1.0183x; 1.0183x over previous
#include <cuda_runtime.h>
#include <cuda_bf16.h>
#include <math.h>
#include <stdint.h>

#define N_NODES 50000
#define N_EDGES 800000
#define NFEAT 512
#define NHID 128
#define NCLASS 40
#define SCAN_BLOCKS ((N_NODES + 1023) / 1024)   // 49

// ---- scratch (static device arrays; no allocation allowed) ----
__device__ float g_S[(size_t)N_NODES * 128];     // xW1 (support1 only, compact)
__device__ float g_T[(size_t)N_NODES * 80];      // [hW2 | hWr2+br2]
__device__ float g_bc1[256];                     // [0 | br1]
__device__ float g_bc2[80];                      // [0 | br2]
// CSR-by-destination build
__device__ int   g_counts[N_NODES];
__device__ int   g_row_start[N_NODES + 1];
__device__ int   g_cursor[N_NODES];
__device__ int   g_bsum[64];
__device__ int   g_es[N_EDGES];
__device__ float g_ev[N_EDGES];
// bf16 split operands for HMMA GEMM1
__device__ __align__(16) __nv_bfloat16 g_Ah[(size_t)N_NODES * NFEAT];
__device__ __align__(16) __nv_bfloat16 g_Al[(size_t)N_NODES * NFEAT];
__device__ __align__(16) __nv_bfloat16 g_Bth[256 * NFEAT];   // [n][k] W1|Wr1 hi
__device__ __align__(16) __nv_bfloat16 g_Btl[256 * NFEAT];   // lo
// bf16 split operands for HMMA GEMM2
__device__ __align__(16) __nv_bfloat16 g_Hh[(size_t)N_NODES * 256];  // h hi
__device__ __align__(16) __nv_bfloat16 g_Hl[(size_t)N_NODES * 256];  // h lo
__device__ __align__(16) __nv_bfloat16 g_W2th[80 * 256];     // [n][k] W2|Wr2 hi
__device__ __align__(16) __nv_bfloat16 g_W2tl[80 * 256];     // lo

// ================= helpers =================
__device__ __forceinline__ uint32_t smem_u32(const void* p) {
    uint32_t a;
    asm("{ .reg .u64 t; cvta.to.shared.u64 t, %1; cvt.u32.u64 %0, t; }" : "=r"(a) : "l"(p));
    return a;
}
#define CP_ASYNC16(dst, src) \
    asm volatile("cp.async.cg.shared.global [%0], [%1], 16;" :: "r"(dst), "l"(src) : "memory")
#define CP_COMMIT() asm volatile("cp.async.commit_group;" ::: "memory")
#define CP_WAIT(n)  asm volatile("cp.async.wait_group %0;" :: "n"(n) : "memory")

__device__ __forceinline__ void ldmx4(uint32_t addr, uint32_t& r0, uint32_t& r1,
                                      uint32_t& r2, uint32_t& r3) {
    asm volatile("ldmatrix.sync.aligned.m8n8.x4.shared.b16 {%0,%1,%2,%3}, [%4];"
                 : "=r"(r0), "=r"(r1), "=r"(r2), "=r"(r3) : "r"(addr));
}
__device__ __forceinline__ void ldmx2(uint32_t addr, uint32_t& r0, uint32_t& r1) {
    asm volatile("ldmatrix.sync.aligned.m8n8.x2.shared.b16 {%0,%1}, [%2];"
                 : "=r"(r0), "=r"(r1) : "r"(addr));
}
__device__ __forceinline__ void mma16816(float& c0, float& c1, float& c2, float& c3,
                                         uint32_t a0, uint32_t a1, uint32_t a2, uint32_t a3,
                                         uint32_t b0, uint32_t b1) {
    asm volatile("mma.sync.aligned.m16n8k16.row.col.f32.bf16.bf16.f32 "
                 "{%0,%1,%2,%3}, {%4,%5,%6,%7}, {%8,%9}, {%0,%1,%2,%3};"
                 : "+f"(c0), "+f"(c1), "+f"(c2), "+f"(c3)
                 : "r"(a0), "r"(a1), "r"(a2), "r"(a3), "r"(b0), "r"(b1));
}
// split float4 -> 4 hi bf16 (uint2) + 4 lo bf16 (uint2)
__device__ __forceinline__ void split4(float4 f, uint2& hi, uint2& lo) {
    __nv_bfloat16 h0 = __float2bfloat16(f.x), h1 = __float2bfloat16(f.y);
    __nv_bfloat16 h2 = __float2bfloat16(f.z), h3 = __float2bfloat16(f.w);
    __nv_bfloat16 l0 = __float2bfloat16(f.x - __bfloat162float(h0));
    __nv_bfloat16 l1 = __float2bfloat16(f.y - __bfloat162float(h1));
    __nv_bfloat16 l2 = __float2bfloat16(f.z - __bfloat162float(h2));
    __nv_bfloat16 l3 = __float2bfloat16(f.w - __bfloat162float(h3));
    union { __nv_bfloat162 b; uint32_t u; } p;
    p.b.x = h0; p.b.y = h1; hi.x = p.u;
    p.b.x = h2; p.b.y = h3; hi.y = p.u;
    p.b.x = l0; p.b.y = l1; lo.x = p.u;
    p.b.x = l2; p.b.y = l3; lo.y = p.u;
}
// split float2 -> packed bf16x2 hi + lo
__device__ __forceinline__ void split2(float a, float b, uint32_t& hi, uint32_t& lo) {
    __nv_bfloat16 h0 = __float2bfloat16(a), h1 = __float2bfloat16(b);
    __nv_bfloat16 l0 = __float2bfloat16(a - __bfloat162float(h0));
    __nv_bfloat16 l1 = __float2bfloat16(b - __bfloat162float(h1));
    union { __nv_bfloat162 b; uint32_t u; } p;
    p.b.x = h0; p.b.y = h1; hi = p.u;
    p.b.x = l0; p.b.y = l1; lo = p.u;
}

// ---- pack: B1t hi/lo, W2t hi/lo, biases ----
__global__ void pack_kernel(const float* __restrict__ W1, const float* __restrict__ Wr1,
                            const float* __restrict__ br1,
                            const float* __restrict__ W2, const float* __restrict__ Wr2,
                            const float* __restrict__ br2) {
    int idx = blockIdx.x * blockDim.x + threadIdx.x;
    if (idx < NFEAT * 256) {
        int k = idx >> 8, n = idx & 255;
        float w = (n < 128) ? W1[k * 128 + n] : Wr1[k * 128 + (n - 128)];
        __nv_bfloat16 hi = __float2bfloat16(w);
        __nv_bfloat16 lo = __float2bfloat16(w - __bfloat162float(hi));
        g_Bth[(size_t)n * NFEAT + k] = hi;
        g_Btl[(size_t)n * NFEAT + k] = lo;
    }
    if (idx < 256 * 80) {
        int k = idx / 80, j = idx % 80;
        float w = (j < 40) ? W2[k * 40 + j] : Wr2[k * 40 + (j - 40)];
        __nv_bfloat16 hi = __float2bfloat16(w);
        __nv_bfloat16 lo = __float2bfloat16(w - __bfloat162float(hi));
        g_W2th[j * 256 + k] = hi;
        g_W2tl[j * 256 + k] = lo;
    }
    if (idx < 256) g_bc1[idx] = (idx < 128) ? 0.f : br1[idx - 128];
    if (idx < 80)  g_bc2[idx] = (idx < 40) ? 0.f : br2[idx - 40];
}

// ---- zero histogram (side chain) ----
__global__ void zero_counts_kernel() {
    int i = blockIdx.x * blockDim.x + threadIdx.x;
    if (i < N_NODES) g_counts[i] = 0;
}

// ---- convert x -> Ah, Al (bf16 hi/lo), row-major ----
__global__ void convertA_kernel(const float* __restrict__ x) {
    int gid = blockIdx.x * blockDim.x + threadIdx.x;  // 8 fp32 per thread
    if (gid >= N_NODES * (NFEAT / 8)) return;
    const float4* p = (const float4*)&x[(size_t)gid * 8];
    uint2 h0, l0, h1, l1;
    split4(p[0], h0, l0);
    split4(p[1], h1, l1);
    *(uint4*)&g_Ah[(size_t)gid * 8] = make_uint4(h0.x, h0.y, h1.x, h1.y);
    *(uint4*)&g_Al[(size_t)gid * 8] = make_uint4(l0.x, l0.y, l1.x, l1.y);
}

// ---- GEMM1 via mma.sync bf16 3-term ----
// blockIdx.y==0: S[:, :128] compact fp32 (spmm1 gather source)
// blockIdx.y==1: residual half -> Hh/Hl[:,128:] directly (bias-added bf16 split)
#define ARR_SZ (128 * 40 * 2)        // bytes per smem array (80B padded rows)
#define STG_SZ (4 * ARR_SZ)          // 40960
#define GEMM1_SMEM (2 * STG_SZ)      // 81920

__global__ __launch_bounds__(256, 2) void gemm1_mma() {
    extern __shared__ unsigned char smem[];
    uint32_t sb = smem_u32(smem);
    int tid = threadIdx.x, lane = tid & 31, wid = tid >> 5;
    int warp_m = wid & 3, warp_n = wid >> 2;
    int brow = blockIdx.x * 128;
    int bcol = blockIdx.y * 128;
    int grp = lane >> 3, rr = lane & 7;

    float acc[2][8][4];
#pragma unroll
    for (int i = 0; i < 2; i++)
#pragma unroll
        for (int j = 0; j < 8; j++)
#pragma unroll
            for (int q = 0; q < 4; q++) acc[i][j][q] = 0.f;

    const __nv_bfloat16* gsrc[4] = {g_Ah, g_Al, g_Bth, g_Btl};

#define LOAD_STAGE(stage, k0) do { \
    _Pragma("unroll") \
    for (int arr = 0; arr < 4; arr++) { \
        _Pragma("unroll") \
        for (int rep = 0; rep < 2; rep++) { \
            int q = tid + rep * 256; \
            int row = q >> 2, c16 = q & 3; \
            uint32_t dst = sb + (stage) * STG_SZ + arr * ARR_SZ + row * 80 + c16 * 16; \
            const __nv_bfloat16* src; \
            if (arr < 2) { \
                int rg = brow + row; if (rg >= N_NODES) rg = N_NODES - 1; \
                src = gsrc[arr] + (size_t)rg * NFEAT + (k0) + c16 * 8; \
            } else { \
                src = gsrc[arr] + (size_t)(bcol + row) * NFEAT + (k0) + c16 * 8; \
            } \
            CP_ASYNC16(dst, src); \
        } \
    } \
    CP_COMMIT(); \
} while (0)

    LOAD_STAGE(0, 0);

    int cur = 0;
    for (int s = 0; s < 16; s++) {
        if (s < 15) {
            LOAD_STAGE(1 - cur, (s + 1) * 32);
            CP_WAIT(1);
        } else {
            CP_WAIT(0);
        }
        __syncthreads();

        uint32_t base = sb + cur * STG_SZ;
#pragma unroll
        for (int k16 = 0; k16 < 32; k16 += 16) {
            uint32_t ah[2][4], al[2][4], bh[4][4], bl[4][4];
#pragma unroll
            for (int mi = 0; mi < 2; mi++) {
                uint32_t ao = base + (uint32_t)((warp_m * 32 + mi * 16 + (grp & 1) * 8 + rr) * 80
                                                + (k16 + (grp >> 1) * 8) * 2);
                ldmx4(ao + 0 * ARR_SZ, ah[mi][0], ah[mi][1], ah[mi][2], ah[mi][3]);
                ldmx4(ao + 1 * ARR_SZ, al[mi][0], al[mi][1], al[mi][2], al[mi][3]);
            }
#pragma unroll
            for (int p = 0; p < 4; p++) {
                uint32_t bo = base + (uint32_t)((warp_n * 64 + p * 16 + (grp >> 1) * 8 + rr) * 80
                                                + (k16 + (grp & 1) * 8) * 2);
                ldmx4(bo + 2 * ARR_SZ, bh[p][0], bh[p][1], bh[p][2], bh[p][3]);
                ldmx4(bo + 3 * ARR_SZ, bl[p][0], bl[p][1], bl[p][2], bl[p][3]);
            }
#pragma unroll
            for (int mi = 0; mi < 2; mi++) {
#pragma unroll
                for (int ni = 0; ni < 8; ni++) {
                    uint32_t b0h = bh[ni >> 1][(ni & 1) * 2], b1h = bh[ni >> 1][(ni & 1) * 2 + 1];
                    uint32_t b0l = bl[ni >> 1][(ni & 1) * 2], b1l = bl[ni >> 1][(ni & 1) * 2 + 1];
                    float* c = acc[mi][ni];
                    mma16816(c[0], c[1], c[2], c[3],
                             ah[mi][0], ah[mi][1], ah[mi][2], ah[mi][3], b0h, b1h);
                    mma16816(c[0], c[1], c[2], c[3],
                             ah[mi][0], ah[mi][1], ah[mi][2], ah[mi][3], b0l, b1l);
                    mma16816(c[0], c[1], c[2], c[3],
                             al[mi][0], al[mi][1], al[mi][2], al[mi][3], b0h, b1h);
                }
            }
        }
        __syncthreads();
        cur ^= 1;
    }

#pragma unroll
    for (int mi = 0; mi < 2; mi++) {
        int r0 = brow + warp_m * 32 + mi * 16 + (lane >> 2);
#pragma unroll
        for (int ni = 0; ni < 8; ni++) {
            int c = bcol + warp_n * 64 + ni * 8 + (lane & 3) * 2;
            float bx = g_bc1[c], by = g_bc1[c + 1];
            float* cc = acc[mi][ni];
            if (blockIdx.y == 0) {
                if (r0 < N_NODES)
                    *(float2*)&g_S[(size_t)r0 * 128 + c] = make_float2(cc[0] + bx, cc[1] + by);
                if (r0 + 8 < N_NODES)
                    *(float2*)&g_S[(size_t)(r0 + 8) * 128 + c] = make_float2(cc[2] + bx, cc[3] + by);
            } else {
                uint32_t hi, lo;
                if (r0 < N_NODES) {
                    split2(cc[0] + bx, cc[1] + by, hi, lo);
                    *(uint32_t*)&g_Hh[(size_t)r0 * 256 + c] = hi;
                    *(uint32_t*)&g_Hl[(size_t)r0 * 256 + c] = lo;
                }
                if (r0 + 8 < N_NODES) {
                    split2(cc[2] + bx, cc[3] + by, hi, lo);
                    *(uint32_t*)&g_Hh[(size_t)(r0 + 8) * 256 + c] = hi;
                    *(uint32_t*)&g_Hl[(size_t)(r0 + 8) * 256 + c] = lo;
                }
            }
        }
    }
}

// ---- GEMM2 via mma.sync bf16 3-term: g_T = h @ [W2|Wr2] + [0|br2] ----
#define A2_SZ (128 * 80)             // 10240 bytes (hi or lo)
#define B2_SZ (80 * 80)              // 6400 bytes
#define STG2_SZ (2 * A2_SZ + 2 * B2_SZ)  // 33280
#define G2_BOFF (2 * A2_SZ)
#define GEMM2_SMEM (2 * STG2_SZ)     // 66560

__global__ __launch_bounds__(256, 2) void gemm2_mma() {
    extern __shared__ unsigned char smem[];
    uint32_t sb = smem_u32(smem);
    int tid = threadIdx.x, lane = tid & 31, wid = tid >> 5;
    int warp_m = wid & 3, warp_n = wid >> 2;
    int brow = blockIdx.x * 128;
    int grp = lane >> 3, rr = lane & 7;

    float acc[2][5][4];
#pragma unroll
    for (int i = 0; i < 2; i++)
#pragma unroll
        for (int j = 0; j < 5; j++)
#pragma unroll
            for (int q = 0; q < 4; q++) acc[i][j][q] = 0.f;

#define LOAD_STAGE2(stage, k0) do { \
    _Pragma("unroll") \
    for (int arr = 0; arr < 2; arr++) { \
        _Pragma("unroll") \
        for (int rep = 0; rep < 2; rep++) { \
            int q = tid + rep * 256; \
            int row = q >> 2, c16 = q & 3; \
            int rg = brow + row; if (rg >= N_NODES) rg = N_NODES - 1; \
            uint32_t dst = sb + (stage) * STG2_SZ + arr * A2_SZ + row * 80 + c16 * 16; \
            const __nv_bfloat16* src = (arr ? g_Hl : g_Hh) + (size_t)rg * 256 + (k0) + c16 * 8; \
            CP_ASYNC16(dst, src); \
        } \
    } \
    _Pragma("unroll") \
    for (int arr = 0; arr < 2; arr++) { \
        _Pragma("unroll") \
        for (int rep = 0; rep < 2; rep++) { \
            int q = tid + rep * 256; \
            if (q < 320) { \
                int row = q >> 2, c16 = q & 3; \
                uint32_t dst = sb + (stage) * STG2_SZ + G2_BOFF + arr * B2_SZ + row * 80 + c16 * 16; \
                const __nv_bfloat16* src = (arr ? g_W2tl : g_W2th) + row * 256 + (k0) + c16 * 8; \
                CP_ASYNC16(dst, src); \
            } \
        } \
    } \
    CP_COMMIT(); \
} while (0)

    LOAD_STAGE2(0, 0);

    int cur = 0;
    for (int s = 0; s < 8; s++) {
        if (s < 7) {
            LOAD_STAGE2(1 - cur, (s + 1) * 32);
            CP_WAIT(1);
        } else {
            CP_WAIT(0);
        }
        __syncthreads();

        uint32_t base = sb + cur * STG2_SZ;
#pragma unroll
        for (int k16 = 0; k16 < 32; k16 += 16) {
            uint32_t ah[2][4], al[2][4], bh[2][4], bl[2][4], bhx[2], blx[2];
#pragma unroll
            for (int mi = 0; mi < 2; mi++) {
                uint32_t ao = base + (uint32_t)((warp_m * 32 + mi * 16 + (grp & 1) * 8 + rr) * 80
                                                + (k16 + (grp >> 1) * 8) * 2);
                ldmx4(ao + 0 * A2_SZ, ah[mi][0], ah[mi][1], ah[mi][2], ah[mi][3]);
                ldmx4(ao + 1 * A2_SZ, al[mi][0], al[mi][1], al[mi][2], al[mi][3]);
            }
#pragma unroll
            for (int p = 0; p < 2; p++) {
                uint32_t bo = base + G2_BOFF
                            + (uint32_t)((warp_n * 40 + p * 16 + (grp >> 1) * 8 + rr) * 80
                                         + (k16 + (grp & 1) * 8) * 2);
                ldmx4(bo + 0 * B2_SZ, bh[p][0], bh[p][1], bh[p][2], bh[p][3]);
                ldmx4(bo + 1 * B2_SZ, bl[p][0], bl[p][1], bl[p][2], bl[p][3]);
            }
            {
                uint32_t bo = base + G2_BOFF
                            + (uint32_t)((warp_n * 40 + 32 + rr) * 80
                                         + (k16 + (grp & 1) * 8) * 2);
                ldmx2(bo + 0 * B2_SZ, bhx[0], bhx[1]);
                ldmx2(bo + 1 * B2_SZ, blx[0], blx[1]);
            }
#pragma unroll
            for (int mi = 0; mi < 2; mi++) {
#pragma unroll
                for (int ni = 0; ni < 5; ni++) {
                    uint32_t b0h, b1h, b0l, b1l;
                    if (ni < 4) {
                        b0h = bh[ni >> 1][(ni & 1) * 2]; b1h = bh[ni >> 1][(ni & 1) * 2 + 1];
                        b0l = bl[ni >> 1][(ni & 1) * 2]; b1l = bl[ni >> 1][(ni & 1) * 2 + 1];
                    } else {
                        b0h = bhx[0]; b1h = bhx[1];
                        b0l = blx[0]; b1l = blx[1];
                    }
                    float* c = acc[mi][ni];
                    mma16816(c[0], c[1], c[2], c[3],
                             ah[mi][0], ah[mi][1], ah[mi][2], ah[mi][3], b0h, b1h);
                    mma16816(c[0], c[1], c[2], c[3],
                             ah[mi][0], ah[mi][1], ah[mi][2], ah[mi][3], b0l, b1l);
                    mma16816(c[0], c[1], c[2], c[3],
                             al[mi][0], al[mi][1], al[mi][2], al[mi][3], b0h, b1h);
                }
            }
        }
        __syncthreads();
        cur ^= 1;
    }

#pragma unroll
    for (int mi = 0; mi < 2; mi++) {
        int r0 = brow + warp_m * 32 + mi * 16 + (lane >> 2);
#pragma unroll
        for (int ni = 0; ni < 5; ni++) {
            int c = warp_n * 40 + ni * 8 + (lane & 3) * 2;
            float bx = g_bc2[c], by = g_bc2[c + 1];
            float* cc = acc[mi][ni];
            if (r0 < N_NODES)
                *(float2*)&g_T[(size_t)r0 * 80 + c] = make_float2(cc[0] + bx, cc[1] + by);
            if (r0 + 8 < N_NODES)
                *(float2*)&g_T[(size_t)(r0 + 8) * 80 + c] = make_float2(cc[2] + bx, cc[3] + by);
        }
    }
}

// ---- histogram ----
__global__ void hist_kernel(const int* __restrict__ dst) {
    int e = blockIdx.x * blockDim.x + threadIdx.x;
    if (e < N_EDGES) atomicAdd(&g_counts[dst[e]], 1);
}

// ---- parallel 3-phase scan ----
__global__ void scan1_kernel() {
    __shared__ int wsum[32];
    int tid = threadIdx.x, lane = tid & 31, w = tid >> 5;
    int i = blockIdx.x * 1024 + tid;
    int c = (i < N_NODES) ? g_counts[i] : 0;
    int v = c;
#pragma unroll
    for (int d = 1; d < 32; d <<= 1) {
        int t = __shfl_up_sync(0xffffffffu, v, d);
        if (lane >= d) v += t;
    }
    if (lane == 31) wsum[w] = v;
    __syncthreads();
    if (w == 0) {
        int s = wsum[lane];
#pragma unroll
        for (int d = 1; d < 32; d <<= 1) {
            int t = __shfl_up_sync(0xffffffffu, s, d);
            if (lane >= d) s += t;
        }
        wsum[lane] = s;
    }
    __syncthreads();
    int incl = v + ((w == 0) ? 0 : wsum[w - 1]);
    if (i < N_NODES) g_row_start[i] = incl - c;
    if (tid == 1023) g_bsum[blockIdx.x] = incl;
}

__global__ void scan2_kernel() {
    int lane = threadIdx.x;
    int a = (2 * lane < SCAN_BLOCKS) ? g_bsum[2 * lane] : 0;
    int b = (2 * lane + 1 < SCAN_BLOCKS) ? g_bsum[2 * lane + 1] : 0;
    int pair = a + b;
    int v = pair;
#pragma unroll
    for (int d = 1; d < 32; d <<= 1) {
        int t = __shfl_up_sync(0xffffffffu, v, d);
        if (lane >= d) v += t;
    }
    int excl = v - pair;
    if (2 * lane < 64) g_bsum[2 * lane] = excl;
    if (2 * lane + 1 < 64) g_bsum[2 * lane + 1] = excl + a;
}

__global__ void scan3_kernel() {
    int i = blockIdx.x * blockDim.x + threadIdx.x;
    if (i < N_NODES) {
        int v = g_row_start[i] + g_bsum[i >> 10];
        g_row_start[i] = v;
        g_cursor[i] = v;
    }
    if (i == 0) g_row_start[N_NODES] = N_EDGES;
}

__global__ void scatter_kernel(const int* __restrict__ src, const int* __restrict__ dst,
                               const float* __restrict__ val) {
    int e = blockIdx.x * blockDim.x + threadIdx.x;
    if (e >= N_EDGES) return;
    int d = dst[e];
    int p = atomicAdd(&g_cursor[d], 1);
    g_es[p] = src[e];
    g_ev[p] = val[e];
}

// ---- SpMM1 (CSR, warp per dst row, 4-edge unroll): writes bf16 hi/lo h[:, :128] ----
__global__ void spmm1_csr(const float* __restrict__ b1) {
    int w = (blockIdx.x * blockDim.x + threadIdx.x) >> 5;
    int lane = threadIdx.x & 31;
    if (w >= N_NODES) return;
    int e = g_row_start[w];
    int end = g_row_start[w + 1];
    float4 acc = *(const float4*)&b1[lane * 4];
    for (; e + 4 <= end; e += 4) {
        int s0 = g_es[e], s1 = g_es[e + 1], s2 = g_es[e + 2], s3 = g_es[e + 3];
        float v0 = g_ev[e], v1 = g_ev[e + 1], v2 = g_ev[e + 2], v3 = g_ev[e + 3];
        float4 x0 = *(const float4*)&g_S[(size_t)s0 * 128 + lane * 4];
        float4 x1 = *(const float4*)&g_S[(size_t)s1 * 128 + lane * 4];
        float4 x2 = *(const float4*)&g_S[(size_t)s2 * 128 + lane * 4];
        float4 x3 = *(const float4*)&g_S[(size_t)s3 * 128 + lane * 4];
        acc.x = fmaf(v0, x0.x, acc.x); acc.y = fmaf(v0, x0.y, acc.y);
        acc.z = fmaf(v0, x0.z, acc.z); acc.w = fmaf(v0, x0.w, acc.w);
        acc.x = fmaf(v1, x1.x, acc.x); acc.y = fmaf(v1, x1.y, acc.y);
        acc.z = fmaf(v1, x1.z, acc.z); acc.w = fmaf(v1, x1.w, acc.w);
        acc.x = fmaf(v2, x2.x, acc.x); acc.y = fmaf(v2, x2.y, acc.y);
        acc.z = fmaf(v2, x2.z, acc.z); acc.w = fmaf(v2, x2.w, acc.w);
        acc.x = fmaf(v3, x3.x, acc.x); acc.y = fmaf(v3, x3.y, acc.y);
        acc.z = fmaf(v3, x3.z, acc.z); acc.w = fmaf(v3, x3.w, acc.w);
    }
    for (; e < end; e++) {
        int s0 = g_es[e];
        float v0 = g_ev[e];
        float4 x0 = *(const float4*)&g_S[(size_t)s0 * 128 + lane * 4];
        acc.x = fmaf(v0, x0.x, acc.x); acc.y = fmaf(v0, x0.y, acc.y);
        acc.z = fmaf(v0, x0.z, acc.z); acc.w = fmaf(v0, x0.w, acc.w);
    }
    float4 o;
    o.x = fmaxf(acc.x, 0.f); o.y = fmaxf(acc.y, 0.f);
    o.z = fmaxf(acc.z, 0.f); o.w = fmaxf(acc.w, 0.f);
    uint2 hi, lo;
    split4(o, hi, lo);
    *(uint2*)&g_Hh[(size_t)w * 256 + lane * 4] = hi;
    *(uint2*)&g_Hl[(size_t)w * 256 + lane * 4] = lo;
}

// ---- SpMM2 (CSR, warp per dst row, 4-edge unroll) fused final -> out ----
__global__ void spmm2_final(const float* __restrict__ b2, float* __restrict__ out) {
    int w = (blockIdx.x * blockDim.x + threadIdx.x) >> 5;
    int lane = threadIdx.x & 31;
    if (w >= N_NODES) return;
    int e = g_row_start[w];
    int end = g_row_start[w + 1];
    bool act = lane < 20;
    float ax = 0.f, ay = 0.f;
    if (act) { ax = b2[2 * lane]; ay = b2[2 * lane + 1]; }
    for (; e + 4 <= end; e += 4) {
        int s0 = g_es[e], s1 = g_es[e + 1], s2 = g_es[e + 2], s3 = g_es[e + 3];
        float v0 = g_ev[e], v1 = g_ev[e + 1], v2 = g_ev[e + 2], v3 = g_ev[e + 3];
        if (act) {
            float2 t0 = *(const float2*)&g_T[(size_t)s0 * 80 + 2 * lane];
            float2 t1 = *(const float2*)&g_T[(size_t)s1 * 80 + 2 * lane];
            float2 t2 = *(const float2*)&g_T[(size_t)s2 * 80 + 2 * lane];
            float2 t3 = *(const float2*)&g_T[(size_t)s3 * 80 + 2 * lane];
            ax = fmaf(v0, t0.x, ax); ay = fmaf(v0, t0.y, ay);
            ax = fmaf(v1, t1.x, ax); ay = fmaf(v1, t1.y, ay);
            ax = fmaf(v2, t2.x, ax); ay = fmaf(v2, t2.y, ay);
            ax = fmaf(v3, t3.x, ax); ay = fmaf(v3, t3.y, ay);
        }
    }
    for (; e < end; e++) {
        int s0 = g_es[e];
        float v0 = g_ev[e];
        if (act) {
            float2 t0 = *(const float2*)&g_T[(size_t)s0 * 80 + 2 * lane];
            ax = fmaf(v0, t0.x, ax); ay = fmaf(v0, t0.y, ay);
        }
    }
    if (act) {
        float2 r = *(const float2*)&g_T[(size_t)w * 80 + 40 + 2 * lane];
        ax += r.x; ay += r.y;
    }
    float m = act ? fmaxf(ax, ay) : -INFINITY;
#pragma unroll
    for (int o = 16; o > 0; o >>= 1) m = fmaxf(m, __shfl_xor_sync(0xffffffffu, m, o));
    float s = act ? (__expf(ax - m) + __expf(ay - m)) : 0.f;
#pragma unroll
    for (int o = 16; o > 0; o >>= 1) s += __shfl_xor_sync(0xffffffffu, s, o);
    float lse = m + logf(s);
    if (act) {
        out[(size_t)w * 40 + 2 * lane + 0] = ax - lse;
        out[(size_t)w * 40 + 2 * lane + 1] = ay - lse;
    }
}

extern "C" void kernel_launch(void* const* d_in, const int* in_sizes, int n_in,
                              void* d_out, int out_size) {
    const float* x    = (const float*)d_in[0];
    const int*   esrc = (const int*)d_in[1];
    const int*   edst = (const int*)d_in[2];
    const float* eval_= (const float*)d_in[3];
    const float* W1   = (const float*)d_in[4];
    const float* b1   = (const float*)d_in[5];
    const float* Wr1  = (const float*)d_in[6];
    const float* br1  = (const float*)d_in[7];
    const float* W2   = (const float*)d_in[8];
    const float* b2   = (const float*)d_in[9];
    const float* Wr2  = (const float*)d_in[10];
    const float* br2  = (const float*)d_in[11];
    float* out = (float*)d_out;

    static cudaStream_t s_side = nullptr;
    static cudaEvent_t ev_fork = nullptr, ev_join = nullptr;
    static bool init_done = false;
    if (!init_done) {
        cudaFuncSetAttribute(gemm1_mma, cudaFuncAttributeMaxDynamicSharedMemorySize, GEMM1_SMEM);
        cudaFuncSetAttribute(gemm2_mma, cudaFuncAttributeMaxDynamicSharedMemorySize, GEMM2_SMEM);
        cudaStreamCreateWithFlags(&s_side, cudaStreamNonBlocking);
        cudaEventCreateWithFlags(&ev_fork, cudaEventDisableTiming);
        cudaEventCreateWithFlags(&ev_join, cudaEventDisableTiming);
        init_done = true;
    }

    // ---- fork: CSR build chain on side stream ----
    cudaEventRecord(ev_fork, 0);
    cudaStreamWaitEvent(s_side, ev_fork, 0);
    zero_counts_kernel<<<(N_NODES + 255) / 256, 256, 0, s_side>>>();
    hist_kernel<<<(N_EDGES + 255) / 256, 256, 0, s_side>>>(edst);
    scan1_kernel<<<SCAN_BLOCKS, 1024, 0, s_side>>>();
    scan2_kernel<<<1, 32, 0, s_side>>>();
    scan3_kernel<<<(N_NODES + 255) / 256, 256, 0, s_side>>>();
    scatter_kernel<<<(N_EDGES + 255) / 256, 256, 0, s_side>>>(esrc, edst, eval_);
    cudaEventRecord(ev_join, s_side);

    // ---- main chain: pack -> convert -> GEMM1 ----
    pack_kernel<<<512, 256>>>(W1, Wr1, br1, W2, Wr2, br2);
    convertA_kernel<<<(N_NODES * (NFEAT / 8) + 255) / 256, 256>>>(x);
    {
        dim3 grid((N_NODES + 127) / 128, 2);
        gemm1_mma<<<grid, 256, GEMM1_SMEM>>>();
    }

    // ---- join: spmm1 needs CSR + S ----
    cudaStreamWaitEvent(0, ev_join, 0);
    spmm1_csr<<<(N_NODES + 7) / 8, 256>>>(b1);
    gemm2_mma<<<(N_NODES + 127) / 128, 256, GEMM2_SMEM>>>();
    spmm2_final<<<(N_NODES + 7) / 8, 256>>>(b2, out);
}

// round 13
// speedup vs baseline: 1.0227x; 1.0044x over previous
#include <cuda_runtime.h>
#include <cuda_bf16.h>
#include <math.h>
#include <stdint.h>

#define N_NODES 50000
#define N_EDGES 800000
#define NFEAT 512
#define NHID 128
#define NCLASS 40
#define SCAN_BLOCKS ((N_NODES + 1023) / 1024)   // 49
#define HALF_NODES 25088                        // 196 * 128

// ---- scratch (static device arrays; no allocation allowed) ----
__device__ float g_S[(size_t)N_NODES * 128];     // xW1 (support1 only, compact)
__device__ float g_T[(size_t)N_NODES * 80];      // [hW2 | hWr2+br2]
__device__ float g_bc1[256];                     // [0 | br1]
__device__ float g_bc2[80];                      // [0 | br2]
// CSR-by-destination build
__device__ int   g_counts[N_NODES];
__device__ int   g_row_start[N_NODES + 1];
__device__ int   g_cursor[N_NODES];
__device__ int   g_bsum[64];
__device__ int   g_es[N_EDGES];
__device__ float g_ev[N_EDGES];
// bf16 split operands for HMMA GEMM1
__device__ __align__(16) __nv_bfloat16 g_Ah[(size_t)N_NODES * NFEAT];
__device__ __align__(16) __nv_bfloat16 g_Al[(size_t)N_NODES * NFEAT];
__device__ __align__(16) __nv_bfloat16 g_Bth[256 * NFEAT];   // [n][k] W1|Wr1 hi
__device__ __align__(16) __nv_bfloat16 g_Btl[256 * NFEAT];   // lo
// bf16 split operands for HMMA GEMM2
__device__ __align__(16) __nv_bfloat16 g_Hh[(size_t)N_NODES * 256];  // h hi
__device__ __align__(16) __nv_bfloat16 g_Hl[(size_t)N_NODES * 256];  // h lo
__device__ __align__(16) __nv_bfloat16 g_W2th[80 * 256];     // [n][k] W2|Wr2 hi
__device__ __align__(16) __nv_bfloat16 g_W2tl[80 * 256];     // lo

// ================= helpers =================
__device__ __forceinline__ uint32_t smem_u32(const void* p) {
    uint32_t a;
    asm("{ .reg .u64 t; cvta.to.shared.u64 t, %1; cvt.u32.u64 %0, t; }" : "=r"(a) : "l"(p));
    return a;
}
#define CP_ASYNC16(dst, src) \
    asm volatile("cp.async.cg.shared.global [%0], [%1], 16;" :: "r"(dst), "l"(src) : "memory")
#define CP_COMMIT() asm volatile("cp.async.commit_group;" ::: "memory")
#define CP_WAIT(n)  asm volatile("cp.async.wait_group %0;" :: "n"(n) : "memory")

__device__ __forceinline__ void ldmx4(uint32_t addr, uint32_t& r0, uint32_t& r1,
                                      uint32_t& r2, uint32_t& r3) {
    asm volatile("ldmatrix.sync.aligned.m8n8.x4.shared.b16 {%0,%1,%2,%3}, [%4];"
                 : "=r"(r0), "=r"(r1), "=r"(r2), "=r"(r3) : "r"(addr));
}
__device__ __forceinline__ void ldmx2(uint32_t addr, uint32_t& r0, uint32_t& r1) {
    asm volatile("ldmatrix.sync.aligned.m8n8.x2.shared.b16 {%0,%1}, [%2];"
                 : "=r"(r0), "=r"(r1) : "r"(addr));
}
__device__ __forceinline__ void mma16816(float& c0, float& c1, float& c2, float& c3,
                                         uint32_t a0, uint32_t a1, uint32_t a2, uint32_t a3,
                                         uint32_t b0, uint32_t b1) {
    asm volatile("mma.sync.aligned.m16n8k16.row.col.f32.bf16.bf16.f32 "
                 "{%0,%1,%2,%3}, {%4,%5,%6,%7}, {%8,%9}, {%0,%1,%2,%3};"
                 : "+f"(c0), "+f"(c1), "+f"(c2), "+f"(c3)
                 : "r"(a0), "r"(a1), "r"(a2), "r"(a3), "r"(b0), "r"(b1));
}
// split float4 -> 4 hi bf16 (uint2) + 4 lo bf16 (uint2)
__device__ __forceinline__ void split4(float4 f, uint2& hi, uint2& lo) {
    __nv_bfloat16 h0 = __float2bfloat16(f.x), h1 = __float2bfloat16(f.y);
    __nv_bfloat16 h2 = __float2bfloat16(f.z), h3 = __float2bfloat16(f.w);
    __nv_bfloat16 l0 = __float2bfloat16(f.x - __bfloat162float(h0));
    __nv_bfloat16 l1 = __float2bfloat16(f.y - __bfloat162float(h1));
    __nv_bfloat16 l2 = __float2bfloat16(f.z - __bfloat162float(h2));
    __nv_bfloat16 l3 = __float2bfloat16(f.w - __bfloat162float(h3));
    union { __nv_bfloat162 b; uint32_t u; } p;
    p.b.x = h0; p.b.y = h1; hi.x = p.u;
    p.b.x = h2; p.b.y = h3; hi.y = p.u;
    p.b.x = l0; p.b.y = l1; lo.x = p.u;
    p.b.x = l2; p.b.y = l3; lo.y = p.u;
}
// split float2 -> packed bf16x2 hi + lo
__device__ __forceinline__ void split2(float a, float b, uint32_t& hi, uint32_t& lo) {
    __nv_bfloat16 h0 = __float2bfloat16(a), h1 = __float2bfloat16(b);
    __nv_bfloat16 l0 = __float2bfloat16(a - __bfloat162float(h0));
    __nv_bfloat16 l1 = __float2bfloat16(b - __bfloat162float(h1));
    union { __nv_bfloat162 b; uint32_t u; } p;
    p.b.x = h0; p.b.y = h1; hi = p.u;
    p.b.x = l0; p.b.y = l1; lo = p.u;
}

// ---- pack: B1t hi/lo, W2t hi/lo, biases ----
__global__ void pack_kernel(const float* __restrict__ W1, const float* __restrict__ Wr1,
                            const float* __restrict__ br1,
                            const float* __restrict__ W2, const float* __restrict__ Wr2,
                            const float* __restrict__ br2) {
    int idx = blockIdx.x * blockDim.x + threadIdx.x;
    if (idx < NFEAT * 256) {
        int k = idx >> 8, n = idx & 255;
        float w = (n < 128) ? W1[k * 128 + n] : Wr1[k * 128 + (n - 128)];
        __nv_bfloat16 hi = __float2bfloat16(w);
        __nv_bfloat16 lo = __float2bfloat16(w - __bfloat162float(hi));
        g_Bth[(size_t)n * NFEAT + k] = hi;
        g_Btl[(size_t)n * NFEAT + k] = lo;
    }
    if (idx < 256 * 80) {
        int k = idx / 80, j = idx % 80;
        float w = (j < 40) ? W2[k * 40 + j] : Wr2[k * 40 + (j - 40)];
        __nv_bfloat16 hi = __float2bfloat16(w);
        __nv_bfloat16 lo = __float2bfloat16(w - __bfloat162float(hi));
        g_W2th[j * 256 + k] = hi;
        g_W2tl[j * 256 + k] = lo;
    }
    if (idx < 256) g_bc1[idx] = (idx < 128) ? 0.f : br1[idx - 128];
    if (idx < 80)  g_bc2[idx] = (idx < 40) ? 0.f : br2[idx - 40];
}

// ---- zero histogram (side chain) ----
__global__ void zero_counts_kernel() {
    int i = blockIdx.x * blockDim.x + threadIdx.x;
    if (i < N_NODES) g_counts[i] = 0;
}

// ---- convert x -> Ah, Al (bf16 hi/lo), row-major ----
__global__ void convertA_kernel(const float* __restrict__ x) {
    int gid = blockIdx.x * blockDim.x + threadIdx.x;  // 8 fp32 per thread
    if (gid >= N_NODES * (NFEAT / 8)) return;
    const float4* p = (const float4*)&x[(size_t)gid * 8];
    uint2 h0, l0, h1, l1;
    split4(p[0], h0, l0);
    split4(p[1], h1, l1);
    *(uint4*)&g_Ah[(size_t)gid * 8] = make_uint4(h0.x, h0.y, h1.x, h1.y);
    *(uint4*)&g_Al[(size_t)gid * 8] = make_uint4(l0.x, l0.y, l1.x, l1.y);
}

// ---- GEMM1 via mma.sync bf16 3-term ----
// blockIdx.y==0: S[:, :128] compact fp32 (spmm1 gather source)
// blockIdx.y==1: residual half -> Hh/Hl[:,128:] directly (bias-added bf16 split)
#define ARR_SZ (128 * 40 * 2)        // bytes per smem array (80B padded rows)
#define STG_SZ (4 * ARR_SZ)          // 40960
#define GEMM1_SMEM (2 * STG_SZ)      // 81920

__global__ __launch_bounds__(256, 2) void gemm1_mma() {
    extern __shared__ unsigned char smem[];
    uint32_t sb = smem_u32(smem);
    int tid = threadIdx.x, lane = tid & 31, wid = tid >> 5;
    int warp_m = wid & 3, warp_n = wid >> 2;
    int brow = blockIdx.x * 128;
    int bcol = blockIdx.y * 128;
    int grp = lane >> 3, rr = lane & 7;

    float acc[2][8][4];
#pragma unroll
    for (int i = 0; i < 2; i++)
#pragma unroll
        for (int j = 0; j < 8; j++)
#pragma unroll
            for (int q = 0; q < 4; q++) acc[i][j][q] = 0.f;

    const __nv_bfloat16* gsrc[4] = {g_Ah, g_Al, g_Bth, g_Btl};

#define LOAD_STAGE(stage, k0) do { \
    _Pragma("unroll") \
    for (int arr = 0; arr < 4; arr++) { \
        _Pragma("unroll") \
        for (int rep = 0; rep < 2; rep++) { \
            int q = tid + rep * 256; \
            int row = q >> 2, c16 = q & 3; \
            uint32_t dst = sb + (stage) * STG_SZ + arr * ARR_SZ + row * 80 + c16 * 16; \
            const __nv_bfloat16* src; \
            if (arr < 2) { \
                int rg = brow + row; if (rg >= N_NODES) rg = N_NODES - 1; \
                src = gsrc[arr] + (size_t)rg * NFEAT + (k0) + c16 * 8; \
            } else { \
                src = gsrc[arr] + (size_t)(bcol + row) * NFEAT + (k0) + c16 * 8; \
            } \
            CP_ASYNC16(dst, src); \
        } \
    } \
    CP_COMMIT(); \
} while (0)

    LOAD_STAGE(0, 0);

    int cur = 0;
    for (int s = 0; s < 16; s++) {
        if (s < 15) {
            LOAD_STAGE(1 - cur, (s + 1) * 32);
            CP_WAIT(1);
        } else {
            CP_WAIT(0);
        }
        __syncthreads();

        uint32_t base = sb + cur * STG_SZ;
#pragma unroll
        for (int k16 = 0; k16 < 32; k16 += 16) {
            uint32_t ah[2][4], al[2][4], bh[4][4], bl[4][4];
#pragma unroll
            for (int mi = 0; mi < 2; mi++) {
                uint32_t ao = base + (uint32_t)((warp_m * 32 + mi * 16 + (grp & 1) * 8 + rr) * 80
                                                + (k16 + (grp >> 1) * 8) * 2);
                ldmx4(ao + 0 * ARR_SZ, ah[mi][0], ah[mi][1], ah[mi][2], ah[mi][3]);
                ldmx4(ao + 1 * ARR_SZ, al[mi][0], al[mi][1], al[mi][2], al[mi][3]);
            }
#pragma unroll
            for (int p = 0; p < 4; p++) {
                uint32_t bo = base + (uint32_t)((warp_n * 64 + p * 16 + (grp >> 1) * 8 + rr) * 80
                                                + (k16 + (grp & 1) * 8) * 2);
                ldmx4(bo + 2 * ARR_SZ, bh[p][0], bh[p][1], bh[p][2], bh[p][3]);
                ldmx4(bo + 3 * ARR_SZ, bl[p][0], bl[p][1], bl[p][2], bl[p][3]);
            }
#pragma unroll
            for (int mi = 0; mi < 2; mi++) {
#pragma unroll
                for (int ni = 0; ni < 8; ni++) {
                    uint32_t b0h = bh[ni >> 1][(ni & 1) * 2], b1h = bh[ni >> 1][(ni & 1) * 2 + 1];
                    uint32_t b0l = bl[ni >> 1][(ni & 1) * 2], b1l = bl[ni >> 1][(ni & 1) * 2 + 1];
                    float* c = acc[mi][ni];
                    mma16816(c[0], c[1], c[2], c[3],
                             ah[mi][0], ah[mi][1], ah[mi][2], ah[mi][3], b0h, b1h);
                    mma16816(c[0], c[1], c[2], c[3],
                             ah[mi][0], ah[mi][1], ah[mi][2], ah[mi][3], b0l, b1l);
                    mma16816(c[0], c[1], c[2], c[3],
                             al[mi][0], al[mi][1], al[mi][2], al[mi][3], b0h, b1h);
                }
            }
        }
        __syncthreads();
        cur ^= 1;
    }

#pragma unroll
    for (int mi = 0; mi < 2; mi++) {
        int r0 = brow + warp_m * 32 + mi * 16 + (lane >> 2);
#pragma unroll
        for (int ni = 0; ni < 8; ni++) {
            int c = bcol + warp_n * 64 + ni * 8 + (lane & 3) * 2;
            float bx = g_bc1[c], by = g_bc1[c + 1];
            float* cc = acc[mi][ni];
            if (blockIdx.y == 0) {
                if (r0 < N_NODES)
                    *(float2*)&g_S[(size_t)r0 * 128 + c] = make_float2(cc[0] + bx, cc[1] + by);
                if (r0 + 8 < N_NODES)
                    *(float2*)&g_S[(size_t)(r0 + 8) * 128 + c] = make_float2(cc[2] + bx, cc[3] + by);
            } else {
                uint32_t hi, lo;
                if (r0 < N_NODES) {
                    split2(cc[0] + bx, cc[1] + by, hi, lo);
                    *(uint32_t*)&g_Hh[(size_t)r0 * 256 + c] = hi;
                    *(uint32_t*)&g_Hl[(size_t)r0 * 256 + c] = lo;
                }
                if (r0 + 8 < N_NODES) {
                    split2(cc[2] + bx, cc[3] + by, hi, lo);
                    *(uint32_t*)&g_Hh[(size_t)(r0 + 8) * 256 + c] = hi;
                    *(uint32_t*)&g_Hl[(size_t)(r0 + 8) * 256 + c] = lo;
                }
            }
        }
    }
}

// ---- GEMM2 via mma.sync bf16 3-term: g_T[row0+...] = h @ [W2|Wr2] + [0|br2] ----
#define A2_SZ (128 * 80)             // 10240 bytes (hi or lo)
#define B2_SZ (80 * 80)              // 6400 bytes
#define STG2_SZ (2 * A2_SZ + 2 * B2_SZ)  // 33280
#define G2_BOFF (2 * A2_SZ)
#define GEMM2_SMEM (2 * STG2_SZ)     // 66560

__global__ __launch_bounds__(256, 2) void gemm2_mma(int row0) {
    extern __shared__ unsigned char smem[];
    uint32_t sb = smem_u32(smem);
    int tid = threadIdx.x, lane = tid & 31, wid = tid >> 5;
    int warp_m = wid & 3, warp_n = wid >> 2;
    int brow = row0 + blockIdx.x * 128;
    int grp = lane >> 3, rr = lane & 7;

    float acc[2][5][4];
#pragma unroll
    for (int i = 0; i < 2; i++)
#pragma unroll
        for (int j = 0; j < 5; j++)
#pragma unroll
            for (int q = 0; q < 4; q++) acc[i][j][q] = 0.f;

#define LOAD_STAGE2(stage, k0) do { \
    _Pragma("unroll") \
    for (int arr = 0; arr < 2; arr++) { \
        _Pragma("unroll") \
        for (int rep = 0; rep < 2; rep++) { \
            int q = tid + rep * 256; \
            int row = q >> 2, c16 = q & 3; \
            int rg = brow + row; if (rg >= N_NODES) rg = N_NODES - 1; \
            uint32_t dst = sb + (stage) * STG2_SZ + arr * A2_SZ + row * 80 + c16 * 16; \
            const __nv_bfloat16* src = (arr ? g_Hl : g_Hh) + (size_t)rg * 256 + (k0) + c16 * 8; \
            CP_ASYNC16(dst, src); \
        } \
    } \
    _Pragma("unroll") \
    for (int arr = 0; arr < 2; arr++) { \
        _Pragma("unroll") \
        for (int rep = 0; rep < 2; rep++) { \
            int q = tid + rep * 256; \
            if (q < 320) { \
                int row = q >> 2, c16 = q & 3; \
                uint32_t dst = sb + (stage) * STG2_SZ + G2_BOFF + arr * B2_SZ + row * 80 + c16 * 16; \
                const __nv_bfloat16* src = (arr ? g_W2tl : g_W2th) + row * 256 + (k0) + c16 * 8; \
                CP_ASYNC16(dst, src); \
            } \
        } \
    } \
    CP_COMMIT(); \
} while (0)

    LOAD_STAGE2(0, 0);

    int cur = 0;
    for (int s = 0; s < 8; s++) {
        if (s < 7) {
            LOAD_STAGE2(1 - cur, (s + 1) * 32);
            CP_WAIT(1);
        } else {
            CP_WAIT(0);
        }
        __syncthreads();

        uint32_t base = sb + cur * STG2_SZ;
#pragma unroll
        for (int k16 = 0; k16 < 32; k16 += 16) {
            uint32_t ah[2][4], al[2][4], bh[2][4], bl[2][4], bhx[2], blx[2];
#pragma unroll
            for (int mi = 0; mi < 2; mi++) {
                uint32_t ao = base + (uint32_t)((warp_m * 32 + mi * 16 + (grp & 1) * 8 + rr) * 80
                                                + (k16 + (grp >> 1) * 8) * 2);
                ldmx4(ao + 0 * A2_SZ, ah[mi][0], ah[mi][1], ah[mi][2], ah[mi][3]);
                ldmx4(ao + 1 * A2_SZ, al[mi][0], al[mi][1], al[mi][2], al[mi][3]);
            }
#pragma unroll
            for (int p = 0; p < 2; p++) {
                uint32_t bo = base + G2_BOFF
                            + (uint32_t)((warp_n * 40 + p * 16 + (grp >> 1) * 8 + rr) * 80
                                         + (k16 + (grp & 1) * 8) * 2);
                ldmx4(bo + 0 * B2_SZ, bh[p][0], bh[p][1], bh[p][2], bh[p][3]);
                ldmx4(bo + 1 * B2_SZ, bl[p][0], bl[p][1], bl[p][2], bl[p][3]);
            }
            {
                uint32_t bo = base + G2_BOFF
                            + (uint32_t)((warp_n * 40 + 32 + rr) * 80
                                         + (k16 + (grp & 1) * 8) * 2);
                ldmx2(bo + 0 * B2_SZ, bhx[0], bhx[1]);
                ldmx2(bo + 1 * B2_SZ, blx[0], blx[1]);
            }
#pragma unroll
            for (int mi = 0; mi < 2; mi++) {
#pragma unroll
                for (int ni = 0; ni < 5; ni++) {
                    uint32_t b0h, b1h, b0l, b1l;
                    if (ni < 4) {
                        b0h = bh[ni >> 1][(ni & 1) * 2]; b1h = bh[ni >> 1][(ni & 1) * 2 + 1];
                        b0l = bl[ni >> 1][(ni & 1) * 2]; b1l = bl[ni >> 1][(ni & 1) * 2 + 1];
                    } else {
                        b0h = bhx[0]; b1h = bhx[1];
                        b0l = blx[0]; b1l = blx[1];
                    }
                    float* c = acc[mi][ni];
                    mma16816(c[0], c[1], c[2], c[3],
                             ah[mi][0], ah[mi][1], ah[mi][2], ah[mi][3], b0h, b1h);
                    mma16816(c[0], c[1], c[2], c[3],
                             ah[mi][0], ah[mi][1], ah[mi][2], ah[mi][3], b0l, b1l);
                    mma16816(c[0], c[1], c[2], c[3],
                             al[mi][0], al[mi][1], al[mi][2], al[mi][3], b0h, b1h);
                }
            }
        }
        __syncthreads();
        cur ^= 1;
    }

#pragma unroll
    for (int mi = 0; mi < 2; mi++) {
        int r0 = brow + warp_m * 32 + mi * 16 + (lane >> 2);
#pragma unroll
        for (int ni = 0; ni < 5; ni++) {
            int c = warp_n * 40 + ni * 8 + (lane & 3) * 2;
            float bx = g_bc2[c], by = g_bc2[c + 1];
            float* cc = acc[mi][ni];
            if (r0 < N_NODES)
                *(float2*)&g_T[(size_t)r0 * 80 + c] = make_float2(cc[0] + bx, cc[1] + by);
            if (r0 + 8 < N_NODES)
                *(float2*)&g_T[(size_t)(r0 + 8) * 80 + c] = make_float2(cc[2] + bx, cc[3] + by);
        }
    }
}

// ---- histogram ----
__global__ void hist_kernel(const int* __restrict__ dst) {
    int e = blockIdx.x * blockDim.x + threadIdx.x;
    if (e < N_EDGES) atomicAdd(&g_counts[dst[e]], 1);
}

// ---- parallel 3-phase scan ----
__global__ void scan1_kernel() {
    __shared__ int wsum[32];
    int tid = threadIdx.x, lane = tid & 31, w = tid >> 5;
    int i = blockIdx.x * 1024 + tid;
    int c = (i < N_NODES) ? g_counts[i] : 0;
    int v = c;
#pragma unroll
    for (int d = 1; d < 32; d <<= 1) {
        int t = __shfl_up_sync(0xffffffffu, v, d);
        if (lane >= d) v += t;
    }
    if (lane == 31) wsum[w] = v;
    __syncthreads();
    if (w == 0) {
        int s = wsum[lane];
#pragma unroll
        for (int d = 1; d < 32; d <<= 1) {
            int t = __shfl_up_sync(0xffffffffu, s, d);
            if (lane >= d) s += t;
        }
        wsum[lane] = s;
    }
    __syncthreads();
    int incl = v + ((w == 0) ? 0 : wsum[w - 1]);
    if (i < N_NODES) g_row_start[i] = incl - c;
    if (tid == 1023) g_bsum[blockIdx.x] = incl;
}

__global__ void scan2_kernel() {
    int lane = threadIdx.x;
    int a = (2 * lane < SCAN_BLOCKS) ? g_bsum[2 * lane] : 0;
    int b = (2 * lane + 1 < SCAN_BLOCKS) ? g_bsum[2 * lane + 1] : 0;
    int pair = a + b;
    int v = pair;
#pragma unroll
    for (int d = 1; d < 32; d <<= 1) {
        int t = __shfl_up_sync(0xffffffffu, v, d);
        if (lane >= d) v += t;
    }
    int excl = v - pair;
    if (2 * lane < 64) g_bsum[2 * lane] = excl;
    if (2 * lane + 1 < 64) g_bsum[2 * lane + 1] = excl + a;
}

__global__ void scan3_kernel() {
    int i = blockIdx.x * blockDim.x + threadIdx.x;
    if (i < N_NODES) {
        int v = g_row_start[i] + g_bsum[i >> 10];
        g_row_start[i] = v;
        g_cursor[i] = v;
    }
    if (i == 0) g_row_start[N_NODES] = N_EDGES;
}

__global__ void scatter_kernel(const int* __restrict__ src, const int* __restrict__ dst,
                               const float* __restrict__ val) {
    int e = blockIdx.x * blockDim.x + threadIdx.x;
    if (e >= N_EDGES) return;
    int d = dst[e];
    int p = atomicAdd(&g_cursor[d], 1);
    g_es[p] = src[e];
    g_ev[p] = val[e];
}

// ---- SpMM1 (CSR, warp per dst row in [ns, ne), 4-edge unroll) -> Hh/Hl[:, :128] ----
__global__ void spmm1_csr(const float* __restrict__ b1, int ns, int ne) {
    int w = ns + ((blockIdx.x * blockDim.x + threadIdx.x) >> 5);
    int lane = threadIdx.x & 31;
    if (w >= ne) return;
    int e = g_row_start[w];
    int end = g_row_start[w + 1];
    float4 acc = *(const float4*)&b1[lane * 4];
    for (; e + 4 <= end; e += 4) {
        int s0 = g_es[e], s1 = g_es[e + 1], s2 = g_es[e + 2], s3 = g_es[e + 3];
        float v0 = g_ev[e], v1 = g_ev[e + 1], v2 = g_ev[e + 2], v3 = g_ev[e + 3];
        float4 x0 = *(const float4*)&g_S[(size_t)s0 * 128 + lane * 4];
        float4 x1 = *(const float4*)&g_S[(size_t)s1 * 128 + lane * 4];
        float4 x2 = *(const float4*)&g_S[(size_t)s2 * 128 + lane * 4];
        float4 x3 = *(const float4*)&g_S[(size_t)s3 * 128 + lane * 4];
        acc.x = fmaf(v0, x0.x, acc.x); acc.y = fmaf(v0, x0.y, acc.y);
        acc.z = fmaf(v0, x0.z, acc.z); acc.w = fmaf(v0, x0.w, acc.w);
        acc.x = fmaf(v1, x1.x, acc.x); acc.y = fmaf(v1, x1.y, acc.y);
        acc.z = fmaf(v1, x1.z, acc.z); acc.w = fmaf(v1, x1.w, acc.w);
        acc.x = fmaf(v2, x2.x, acc.x); acc.y = fmaf(v2, x2.y, acc.y);
        acc.z = fmaf(v2, x2.z, acc.z); acc.w = fmaf(v2, x2.w, acc.w);
        acc.x = fmaf(v3, x3.x, acc.x); acc.y = fmaf(v3, x3.y, acc.y);
        acc.z = fmaf(v3, x3.z, acc.z); acc.w = fmaf(v3, x3.w, acc.w);
    }
    for (; e < end; e++) {
        int s0 = g_es[e];
        float v0 = g_ev[e];
        float4 x0 = *(const float4*)&g_S[(size_t)s0 * 128 + lane * 4];
        acc.x = fmaf(v0, x0.x, acc.x); acc.y = fmaf(v0, x0.y, acc.y);
        acc.z = fmaf(v0, x0.z, acc.z); acc.w = fmaf(v0, x0.w, acc.w);
    }
    float4 o;
    o.x = fmaxf(acc.x, 0.f); o.y = fmaxf(acc.y, 0.f);
    o.z = fmaxf(acc.z, 0.f); o.w = fmaxf(acc.w, 0.f);
    uint2 hi, lo;
    split4(o, hi, lo);
    *(uint2*)&g_Hh[(size_t)w * 256 + lane * 4] = hi;
    *(uint2*)&g_Hl[(size_t)w * 256 + lane * 4] = lo;
}

// ---- SpMM2 (CSR, warp per dst row, 4-edge unroll) fused final -> out ----
__global__ void spmm2_final(const float* __restrict__ b2, float* __restrict__ out) {
    int w = (blockIdx.x * blockDim.x + threadIdx.x) >> 5;
    int lane = threadIdx.x & 31;
    if (w >= N_NODES) return;
    int e = g_row_start[w];
    int end = g_row_start[w + 1];
    bool act = lane < 20;
    float ax = 0.f, ay = 0.f;
    if (act) { ax = b2[2 * lane]; ay = b2[2 * lane + 1]; }
    for (; e + 4 <= end; e += 4) {
        int s0 = g_es[e], s1 = g_es[e + 1], s2 = g_es[e + 2], s3 = g_es[e + 3];
        float v0 = g_ev[e], v1 = g_ev[e + 1], v2 = g_ev[e + 2], v3 = g_ev[e + 3];
        if (act) {
            float2 t0 = *(const float2*)&g_T[(size_t)s0 * 80 + 2 * lane];
            float2 t1 = *(const float2*)&g_T[(size_t)s1 * 80 + 2 * lane];
            float2 t2 = *(const float2*)&g_T[(size_t)s2 * 80 + 2 * lane];
            float2 t3 = *(const float2*)&g_T[(size_t)s3 * 80 + 2 * lane];
            ax = fmaf(v0, t0.x, ax); ay = fmaf(v0, t0.y, ay);
            ax = fmaf(v1, t1.x, ax); ay = fmaf(v1, t1.y, ay);
            ax = fmaf(v2, t2.x, ax); ay = fmaf(v2, t2.y, ay);
            ax = fmaf(v3, t3.x, ax); ay = fmaf(v3, t3.y, ay);
        }
    }
    for (; e < end; e++) {
        int s0 = g_es[e];
        float v0 = g_ev[e];
        if (act) {
            float2 t0 = *(const float2*)&g_T[(size_t)s0 * 80 + 2 * lane];
            ax = fmaf(v0, t0.x, ax); ay = fmaf(v0, t0.y, ay);
        }
    }
    if (act) {
        float2 r = *(const float2*)&g_T[(size_t)w * 80 + 40 + 2 * lane];
        ax += r.x; ay += r.y;
    }
    float m = act ? fmaxf(ax, ay) : -INFINITY;
#pragma unroll
    for (int o = 16; o > 0; o >>= 1) m = fmaxf(m, __shfl_xor_sync(0xffffffffu, m, o));
    float s = act ? (__expf(ax - m) + __expf(ay - m)) : 0.f;
#pragma unroll
    for (int o = 16; o > 0; o >>= 1) s += __shfl_xor_sync(0xffffffffu, s, o);
    float lse = m + logf(s);
    if (act) {
        out[(size_t)w * 40 + 2 * lane + 0] = ax - lse;
        out[(size_t)w * 40 + 2 * lane + 1] = ay - lse;
    }
}

extern "C" void kernel_launch(void* const* d_in, const int* in_sizes, int n_in,
                              void* d_out, int out_size) {
    const float* x    = (const float*)d_in[0];
    const int*   esrc = (const int*)d_in[1];
    const int*   edst = (const int*)d_in[2];
    const float* eval_= (const float*)d_in[3];
    const float* W1   = (const float*)d_in[4];
    const float* b1   = (const float*)d_in[5];
    const float* Wr1  = (const float*)d_in[6];
    const float* br1  = (const float*)d_in[7];
    const float* W2   = (const float*)d_in[8];
    const float* b2   = (const float*)d_in[9];
    const float* Wr2  = (const float*)d_in[10];
    const float* br2  = (const float*)d_in[11];
    float* out = (float*)d_out;

    static cudaStream_t s_side = nullptr, s_aux = nullptr;
    static cudaEvent_t ev_fork = nullptr, ev_join = nullptr, ev_pack = nullptr;
    static cudaEvent_t ev_h0 = nullptr, ev_g0 = nullptr;
    static bool init_done = false;
    if (!init_done) {
        cudaFuncSetAttribute(gemm1_mma, cudaFuncAttributeMaxDynamicSharedMemorySize, GEMM1_SMEM);
        cudaFuncSetAttribute(gemm2_mma, cudaFuncAttributeMaxDynamicSharedMemorySize, GEMM2_SMEM);
        cudaStreamCreateWithFlags(&s_side, cudaStreamNonBlocking);
        cudaStreamCreateWithFlags(&s_aux, cudaStreamNonBlocking);
        cudaEventCreateWithFlags(&ev_fork, cudaEventDisableTiming);
        cudaEventCreateWithFlags(&ev_join, cudaEventDisableTiming);
        cudaEventCreateWithFlags(&ev_pack, cudaEventDisableTiming);
        cudaEventCreateWithFlags(&ev_h0, cudaEventDisableTiming);
        cudaEventCreateWithFlags(&ev_g0, cudaEventDisableTiming);
        init_done = true;
    }

    // ---- fork ----
    cudaEventRecord(ev_fork, 0);
    // side stream: CSR build chain
    cudaStreamWaitEvent(s_side, ev_fork, 0);
    zero_counts_kernel<<<(N_NODES + 255) / 256, 256, 0, s_side>>>();
    hist_kernel<<<(N_EDGES + 255) / 256, 256, 0, s_side>>>(edst);
    scan1_kernel<<<SCAN_BLOCKS, 1024, 0, s_side>>>();
    scan2_kernel<<<1, 32, 0, s_side>>>();
    scan3_kernel<<<(N_NODES + 255) / 256, 256, 0, s_side>>>();
    scatter_kernel<<<(N_EDGES + 255) / 256, 256, 0, s_side>>>(esrc, edst, eval_);
    cudaEventRecord(ev_join, s_side);
    // aux stream: pack (concurrent with convertA)
    cudaStreamWaitEvent(s_aux, ev_fork, 0);
    pack_kernel<<<512, 256, 0, s_aux>>>(W1, Wr1, br1, W2, Wr2, br2);
    cudaEventRecord(ev_pack, s_aux);

    // main: convertA, then (after pack) GEMM1
    convertA_kernel<<<(N_NODES * (NFEAT / 8) + 255) / 256, 256>>>(x);
    cudaStreamWaitEvent(0, ev_pack, 0);
    {
        dim3 grid((N_NODES + 127) / 128, 2);
        gemm1_mma<<<grid, 256, GEMM1_SMEM>>>();
    }

    // join CSR; pipelined spmm1/gemm2 halves
    cudaStreamWaitEvent(0, ev_join, 0);
    spmm1_csr<<<(HALF_NODES + 7) / 8, 256>>>(b1, 0, HALF_NODES);
    cudaEventRecord(ev_h0, 0);
    // aux: gemm2 on half0, overlapping spmm1 half1
    cudaStreamWaitEvent(s_aux, ev_h0, 0);
    gemm2_mma<<<HALF_NODES / 128, 256, GEMM2_SMEM, s_aux>>>(0);
    cudaEventRecord(ev_g0, s_aux);
    // main: spmm1 half1, gemm2 half1
    spmm1_csr<<<(N_NODES - HALF_NODES + 7) / 8, 256>>>(b1, HALF_NODES, N_NODES);
    gemm2_mma<<<(N_NODES - HALF_NODES + 127) / 128, 256, GEMM2_SMEM>>>(HALF_NODES);
    // join gemm2(half0); final
    cudaStreamWaitEvent(0, ev_g0, 0);
    spmm2_final<<<(N_NODES + 7) / 8, 256>>>(b2, out);
}